// round 1
// baseline (speedup 1.0000x reference)
#include <cuda_runtime.h>
#include <math.h>
#include <float.h>

// Problem dims (fixed by the reference)
#define BB  2
#define SS  2048
#define DD  1024
#define HH  16
#define HD  64
#define BH  (BB*HH)          // 32
#define MTOK (BB*SS)         // 4096

// Scratch (device globals: allocation-free rule)
__device__ float g_Q[BH*SS*HD];   // [bh][s][hd]
__device__ float g_K[BH*SS*HD];
__device__ float g_V[BH*SS*HD];
__device__ float g_O[MTOK*DD];    // [b*S+s][d]  (attention output, pre out-proj)

// ---------------------------------------------------------------------------
// Tiled fp32 NT GEMM: C[m][n] = sum_k A[m][k] * W[n][k] + bias[n]
// BM=BN=128, BK=8, 256 threads, 8x8 microtile.
// MODE 0: A = Ain (X), scatter output into g_Q/g_K/g_V head-major (by `which`)
// MODE 1: A = g_O, output row-major into Cout (final output)
// ---------------------------------------------------------------------------
template<int MODE>
__global__ __launch_bounds__(256)
void gemm_kernel(const float* __restrict__ Ain,
                 const float* __restrict__ W,
                 const float* __restrict__ bias,
                 float* __restrict__ Cout,
                 int which)
{
    __shared__ float As[8][128];
    __shared__ float Bs[8][128];

    const float* A = (MODE == 1) ? g_O : Ain;

    const int m0 = blockIdx.y * 128;
    const int n0 = blockIdx.x * 128;
    const int tid = threadIdx.x;
    const int tx = tid & 15;        // 0..15  (n direction)
    const int ty = tid >> 4;        // 0..15  (m direction)
    const int lm = tid >> 1;        // 0..127 row loaded by this thread
    const int lk = (tid & 1) * 4;   // 0 or 4

    float acc[8][8];
#pragma unroll
    for (int i = 0; i < 8; i++)
#pragma unroll
        for (int j = 0; j < 8; j++) acc[i][j] = 0.f;

    const float* Ap = A + (m0 + lm) * DD + lk;
    const float* Wp = W + (n0 + lm) * DD + lk;

    for (int k0 = 0; k0 < DD; k0 += 8) {
        float4 av = *(const float4*)(Ap + k0);
        float4 wv = *(const float4*)(Wp + k0);
        As[lk + 0][lm] = av.x; As[lk + 1][lm] = av.y;
        As[lk + 2][lm] = av.z; As[lk + 3][lm] = av.w;
        Bs[lk + 0][lm] = wv.x; Bs[lk + 1][lm] = wv.y;
        Bs[lk + 2][lm] = wv.z; Bs[lk + 3][lm] = wv.w;
        __syncthreads();

#pragma unroll
        for (int kk = 0; kk < 8; kk++) {
            float a[8], b[8];
            *(float4*)&a[0] = *(const float4*)&As[kk][ty * 8];
            *(float4*)&a[4] = *(const float4*)&As[kk][ty * 8 + 4];
            *(float4*)&b[0] = *(const float4*)&Bs[kk][tx * 8];
            *(float4*)&b[4] = *(const float4*)&Bs[kk][tx * 8 + 4];
#pragma unroll
            for (int i = 0; i < 8; i++)
#pragma unroll
                for (int j = 0; j < 8; j++)
                    acc[i][j] += a[i] * b[j];
        }
        __syncthreads();
    }

    if (MODE == 0) {
        float* outbuf = (which == 0) ? g_Q : ((which == 1) ? g_K : g_V);
#pragma unroll
        for (int i = 0; i < 8; i++) {
            const int m  = m0 + ty * 8 + i;
            const int b_ = m >> 11;         // /S
            const int s_ = m & 2047;        // %S
#pragma unroll
            for (int j = 0; j < 8; j++) {
                const int n  = n0 + tx * 8 + j;   // 0..1023
                const int h  = n >> 6;
                const int hd = n & 63;
                outbuf[(((b_ * HH + h) * SS) + s_) * HD + hd] = acc[i][j] + bias[n];
            }
        }
    } else {
#pragma unroll
        for (int i = 0; i < 8; i++) {
            const int m = m0 + ty * 8 + i;
            float* cp = Cout + m * DD + n0 + tx * 8;
#pragma unroll
            for (int j = 0; j < 8; j++)
                cp[j] = acc[i][j] + bias[n0 + tx * 8 + j];
        }
    }
}

// ---------------------------------------------------------------------------
// Flash attention (fp32, online softmax).
// Block: 32 query rows of one (b,h); 128 threads = 4 threads per row.
// Key tiles of 32, causal loop kt <= qt; key-padding mask read from input.
// K/V staged in smem with row stride 68 floats (=17*16B: float4-aligned,
// consecutive rows shifted 4 banks -> conflict-free score loads).
// ---------------------------------------------------------------------------
__global__ __launch_bounds__(128)
void attn_kernel(const int* __restrict__ kpm)
{
    __shared__ float Ks[32][68];
    __shared__ float Vs[32][68];
    __shared__ int   pm[32];

    const int qt  = blockIdx.x;      // 0..63
    const int bh  = blockIdx.y;      // 0..31
    const int b_  = bh >> 4;
    const int h   = bh & 15;
    const int tid = threadIdx.x;
    const int lane = tid & 31;
    const int row = (tid >> 5) * 8 + (lane >> 2);  // 0..31
    const int grp = lane & 3;                      // 0..3
    const int qg  = qt * 32 + row;                 // global query index

    // q in registers, pre-scaled by 1/sqrt(HD)
    float q[64];
    {
        const float4* qp = (const float4*)(g_Q + (bh * SS + qg) * HD);
#pragma unroll
        for (int i = 0; i < 16; i++) {
            float4 v = qp[i];
            q[4*i+0] = v.x * 0.125f; q[4*i+1] = v.y * 0.125f;
            q[4*i+2] = v.z * 0.125f; q[4*i+3] = v.w * 0.125f;
        }
    }

    float mrun = -1e30f, lrun = 0.f;
    float o[16];
#pragma unroll
    for (int i = 0; i < 16; i++) o[i] = 0.f;

    const int lr = tid >> 2;         // smem row this thread loads (0..31)
    const int lc = (tid & 3) * 16;   // smem col chunk this thread loads
    const int oc = grp * 16;         // output d-slice owned by this thread

    for (int kt = 0; kt <= qt; ++kt) {
        const int kbase = kt * 32;
        {
            const float4* kp = (const float4*)(g_K + (bh * SS + kbase + lr) * HD + lc);
            const float4* vp = (const float4*)(g_V + (bh * SS + kbase + lr) * HD + lc);
            float4* ksd = (float4*)&Ks[lr][lc];
            float4* vsd = (float4*)&Vs[lr][lc];
#pragma unroll
            for (int c = 0; c < 4; c++) { ksd[c] = kp[c]; vsd[c] = vp[c]; }
            if (tid < 32) pm[tid] = kpm[b_ * SS + kbase + tid];
        }
        __syncthreads();

        // scores for this thread's 8 keys: key = kbase + jj*4 + grp
        float sc[8];
#pragma unroll
        for (int jj = 0; jj < 8; jj++) sc[jj] = 0.f;
#pragma unroll
        for (int d4 = 0; d4 < 16; d4++) {
            const float qx = q[4*d4+0], qy = q[4*d4+1], qz = q[4*d4+2], qw = q[4*d4+3];
#pragma unroll
            for (int jj = 0; jj < 8; jj++) {
                float4 kv = *(const float4*)&Ks[jj * 4 + grp][d4 * 4];
                sc[jj] += qx * kv.x;
                sc[jj] += qy * kv.y;
                sc[jj] += qz * kv.z;
                sc[jj] += qw * kv.w;
            }
        }

        // causal + key-padding mask
        float mloc = -1e30f;
#pragma unroll
        for (int jj = 0; jj < 8; jj++) {
            const int kg = kbase + jj * 4 + grp;
            const bool ok = (kg <= qg) && (pm[jj * 4 + grp] == 0);
            sc[jj] = ok ? sc[jj] : -1e30f;
            mloc = fmaxf(mloc, sc[jj]);
        }
        mloc = fmaxf(mloc, __shfl_xor_sync(0xffffffffu, mloc, 1));
        mloc = fmaxf(mloc, __shfl_xor_sync(0xffffffffu, mloc, 2));

        const float mnew  = fmaxf(mrun, mloc);
        const float alpha = __expf(mrun - mnew);

        float p[8];
        float psum = 0.f;
#pragma unroll
        for (int jj = 0; jj < 8; jj++) { p[jj] = __expf(sc[jj] - mnew); psum += p[jj]; }
        psum += __shfl_xor_sync(0xffffffffu, psum, 1);
        psum += __shfl_xor_sync(0xffffffffu, psum, 2);

        lrun = alpha * lrun + psum;
        mrun = mnew;
#pragma unroll
        for (int i = 0; i < 16; i++) o[i] *= alpha;

        // o[d-slice] += sum over all 32 keys of p_key * V[key][d-slice]
#pragma unroll
        for (int jj = 0; jj < 8; jj++) {
#pragma unroll
            for (int src = 0; src < 4; src++) {
                const float pv = __shfl_sync(0xffffffffu, p[jj], (lane & ~3) | src);
                const float4* vv = (const float4*)&Vs[jj * 4 + src][oc];
#pragma unroll
                for (int c = 0; c < 4; c++) {
                    float4 v4 = vv[c];
                    o[c*4+0] += pv * v4.x;
                    o[c*4+1] += pv * v4.y;
                    o[c*4+2] += pv * v4.z;
                    o[c*4+3] += pv * v4.w;
                }
            }
        }
        __syncthreads();
    }

    const float inv = 1.f / lrun;
    float* op = g_O + (b_ * SS + qg) * DD + h * HD + oc;
#pragma unroll
    for (int c = 0; c < 4; c++) {
        float4 v;
        v.x = o[c*4+0] * inv; v.y = o[c*4+1] * inv;
        v.z = o[c*4+2] * inv; v.w = o[c*4+3] * inv;
        ((float4*)op)[c] = v;
    }
}

// ---------------------------------------------------------------------------
// Launch
// Inputs: 0:X 1:key_padding_mask 2:Wq 3:bq 4:Wk 5:bk 6:Wv 7:bv 8:Wo 9:bo
// ---------------------------------------------------------------------------
extern "C" void kernel_launch(void* const* d_in, const int* in_sizes, int n_in,
                              void* d_out, int out_size)
{
    const float* X   = (const float*)d_in[0];
    const int*   kpm = (const int*)  d_in[1];
    const float* Wq  = (const float*)d_in[2];
    const float* bq  = (const float*)d_in[3];
    const float* Wk  = (const float*)d_in[4];
    const float* bk  = (const float*)d_in[5];
    const float* Wv  = (const float*)d_in[6];
    const float* bv  = (const float*)d_in[7];
    const float* Wo  = (const float*)d_in[8];
    const float* bo  = (const float*)d_in[9];
    float* out = (float*)d_out;

    dim3 gproj(DD / 128, MTOK / 128);   // (8, 32)
    gemm_kernel<0><<<gproj, 256>>>(X, Wq, bq, nullptr, 0);
    gemm_kernel<0><<<gproj, 256>>>(X, Wk, bk, nullptr, 1);
    gemm_kernel<0><<<gproj, 256>>>(X, Wv, bv, nullptr, 2);

    dim3 gattn(SS / 32, BH);            // (64, 32)
    attn_kernel<<<gattn, 128>>>(kpm);

    gemm_kernel<1><<<gproj, 256>>>(nullptr, Wo, bo, out, 3);
}

// round 2
// speedup vs baseline: 5.8717x; 5.8717x over previous
#include <cuda_runtime.h>
#include <math.h>
#include <float.h>
#include <stdint.h>

// Problem dims (fixed by the reference)
#define BB  2
#define SS  2048
#define DD  1024
#define HH  16
#define HD  64
#define BH  (BB*HH)          // 32
#define MTOK (BB*SS)         // 4096

// Scratch (device globals: allocation-free rule)
__device__ float g_Q[BH*SS*HD];   // [bh][s][hd]
__device__ float g_K[BH*SS*HD];
__device__ float g_V[BH*SS*HD];
__device__ float g_O[MTOK*DD];    // [b*S+s][d]  (attention output, pre out-proj)

// ---------------------------------------------------------------------------
// Helpers
// ---------------------------------------------------------------------------
__device__ __forceinline__ uint32_t f2tf(float x) {
    uint32_t r;
    asm("cvt.rna.tf32.f32 %0, %1;" : "=r"(r) : "f"(x));
    return r;
}
__device__ __forceinline__ float tf2f(float x) {  // round fp32 -> tf32 bits, keep as float
    return __uint_as_float(f2tf(x));
}

// D += A * B  (m16n8k8, tf32 inputs as b32 regs, f32 accum)
__device__ __forceinline__ void mma_tf32(float* d, const uint32_t* a, uint32_t b0, uint32_t b1) {
    asm volatile(
        "mma.sync.aligned.m16n8k8.row.col.f32.tf32.tf32.f32 "
        "{%0,%1,%2,%3},{%4,%5,%6,%7},{%8,%9},{%0,%1,%2,%3};"
        : "+f"(d[0]), "+f"(d[1]), "+f"(d[2]), "+f"(d[3])
        : "r"(a[0]), "r"(a[1]), "r"(a[2]), "r"(a[3]), "r"(b0), "r"(b1));
}

// ---------------------------------------------------------------------------
// TF32 tensor-core NT GEMM: C[m][n] = sum_k A[m][k] * W[n][k] + bias[n]
// Block tile 128x128, k-chunk 32. 256 threads = 8 warps (4m x 2n),
// warp tile 32(m) x 64(n) = 2 m16-tiles x 8 n8-tiles.
// Smem stride 36 floats -> all fragment LDS.32 conflict-free.
// MODE 0: output scattered head-major into `headout` ([bh][s][hd])
// MODE 1: A = g_O, output row-major into Cout
// ---------------------------------------------------------------------------
template<int MODE>
__global__ __launch_bounds__(256, 2)
void gemm_tf32(const float* __restrict__ Ain,
               const float* __restrict__ W,
               const float* __restrict__ bias,
               float* __restrict__ Cout)
{
    __shared__ float As[128][36];
    __shared__ float Bs[128][36];

    const float* A = (MODE == 1) ? (const float*)g_O : Ain;

    const int m0 = blockIdx.y * 128;
    const int n0 = blockIdx.x * 128;
    const int tid  = threadIdx.x;
    const int warp = tid >> 5;
    const int lane = tid & 31;
    const int r = lane >> 2;      // 0..7
    const int c = lane & 3;       // 0..3
    const int wm = (warp & 3) * 32;   // warp m offset (4 warps in m)
    const int wn = (warp >> 2) * 64;  // warp n offset (2 warps in n)

    float acc[2][8][4];
#pragma unroll
    for (int mt = 0; mt < 2; mt++)
#pragma unroll
        for (int nt = 0; nt < 8; nt++)
#pragma unroll
            for (int i = 0; i < 4; i++) acc[mt][nt][i] = 0.f;

    for (int k0 = 0; k0 < DD; k0 += 32) {
        // Load A,B tiles (128 rows x 32 k) -> smem, tf32-rounded.
#pragma unroll
        for (int i = 0; i < 4; i++) {
            const int idx = tid + i * 256;
            const int lr  = idx >> 3;          // 0..127
            const int lc4 = (idx & 7) * 4;     // 0,4,..,28
            float4 av = *(const float4*)(A + (m0 + lr) * DD + k0 + lc4);
            float4 wv = *(const float4*)(W + (n0 + lr) * DD + k0 + lc4);
            float4 at, bt;
            at.x = tf2f(av.x); at.y = tf2f(av.y); at.z = tf2f(av.z); at.w = tf2f(av.w);
            bt.x = tf2f(wv.x); bt.y = tf2f(wv.y); bt.z = tf2f(wv.z); bt.w = tf2f(wv.w);
            *(float4*)&As[lr][lc4] = at;
            *(float4*)&Bs[lr][lc4] = bt;
        }
        __syncthreads();

#pragma unroll
        for (int ks = 0; ks < 4; ks++) {
            const int kc = ks * 8;
            uint32_t bf[8][2];
#pragma unroll
            for (int nt = 0; nt < 8; nt++) {
                bf[nt][0] = __float_as_uint(Bs[wn + nt * 8 + r][kc + c]);
                bf[nt][1] = __float_as_uint(Bs[wn + nt * 8 + r][kc + c + 4]);
            }
            uint32_t af[2][4];
#pragma unroll
            for (int mt = 0; mt < 2; mt++) {
                const int mr = wm + mt * 16 + r;
                af[mt][0] = __float_as_uint(As[mr    ][kc + c]);
                af[mt][1] = __float_as_uint(As[mr + 8][kc + c]);
                af[mt][2] = __float_as_uint(As[mr    ][kc + c + 4]);
                af[mt][3] = __float_as_uint(As[mr + 8][kc + c + 4]);
            }
#pragma unroll
            for (int mt = 0; mt < 2; mt++)
#pragma unroll
                for (int nt = 0; nt < 8; nt++)
                    mma_tf32(acc[mt][nt], af[mt], bf[nt][0], bf[nt][1]);
        }
        __syncthreads();
    }

    // Epilogue
#pragma unroll
    for (int mt = 0; mt < 2; mt++) {
        const int m_lo = m0 + wm + mt * 16 + r;
        const int m_hi = m_lo + 8;
#pragma unroll
        for (int nt = 0; nt < 8; nt++) {
            const int n = n0 + wn + nt * 8 + 2 * c;
            const float b0 = bias[n], b1 = bias[n + 1];
            float2 lo = make_float2(acc[mt][nt][0] + b0, acc[mt][nt][1] + b1);
            float2 hi = make_float2(acc[mt][nt][2] + b0, acc[mt][nt][3] + b1);
            if (MODE == 0) {
                const int h  = n >> 6;
                const int hd = n & 63;
                const int blo = m_lo >> 11, slo = m_lo & 2047;
                const int bhi = m_hi >> 11, shi = m_hi & 2047;
                *(float2*)&Cout[(((blo * HH + h) * SS) + slo) * HD + hd] = lo;
                *(float2*)&Cout[(((bhi * HH + h) * SS) + shi) * HD + hd] = hi;
            } else {
                *(float2*)&Cout[m_lo * DD + n] = lo;
                *(float2*)&Cout[m_hi * DD + n] = hi;
            }
        }
    }
}

// ---------------------------------------------------------------------------
// Flash attention with tf32 tensor cores.
// Block: 64 query rows of one (b,h), 128 threads = 4 warps (16 q rows each).
// Key tiles of 32. Q fragments resident in registers. K smem [32][68],
// V smem [32][72] (strides chosen for conflict-free fragment loads),
// P routed through per-warp-private smem (syncwarp only).
// ---------------------------------------------------------------------------
__global__ __launch_bounds__(128, 3)
void attn_tf32(const int* __restrict__ kpm)
{
    __shared__ float Ks[32][68];
    __shared__ float Vs[32][72];
    __shared__ float Ps[64][36];
    __shared__ float msk[32];
    __shared__ int   sflag;

    const int qt = blockIdx.x;          // 0..31 (64 queries each)
    const int bh = blockIdx.y;          // 0..31
    const int b_ = bh >> 4;
    const int h  = bh & 15;
    const int tid  = threadIdx.x;
    const int warp = tid >> 5;
    const int lane = tid & 31;
    const int r = lane >> 2;            // 0..7
    const int c = lane & 3;             // 0..3
    const int q0 = qt * 64;
    const int qr = warp * 16;           // warp's q-row base within block
    const int qg_lo = q0 + qr + r;
    const int qg_hi = qg_lo + 8;

    // Q fragments (scaled by 1/sqrt(HD), tf32-rounded), resident: 8 ksteps x 4
    uint32_t qf[8][4];
    {
        const float* qlo = g_Q + (bh * SS + qg_lo) * HD;
        const float* qhi = g_Q + (bh * SS + qg_hi) * HD;
#pragma unroll
        for (int ks = 0; ks < 8; ks++) {
            qf[ks][0] = f2tf(qlo[ks * 8 + c]     * 0.125f);
            qf[ks][1] = f2tf(qhi[ks * 8 + c]     * 0.125f);
            qf[ks][2] = f2tf(qlo[ks * 8 + c + 4] * 0.125f);
            qf[ks][3] = f2tf(qhi[ks * 8 + c + 4] * 0.125f);
        }
    }

    float o[8][4];
#pragma unroll
    for (int nt = 0; nt < 8; nt++)
#pragma unroll
        for (int i = 0; i < 4; i++) o[nt][i] = 0.f;
    float m_lo = -1e30f, m_hi = -1e30f, l_lo = 0.f, l_hi = 0.f;

    const int kt_max = 2 * qt + 1;      // causal bound for this block
    for (int kt = 0; kt <= kt_max; kt++) {
        const int kbase = kt * 32;

        // ---- stage loads ----
        if (warp == 0) {
            const int pv = kpm[b_ * SS + kbase + lane];
            msk[lane] = pv ? -1e30f : 0.f;
            const int allm = __all_sync(0xffffffffu, pv != 0);
            if (lane == 0) sflag = allm;
        }
#pragma unroll
        for (int i = 0; i < 4; i++) {
            const int idx = tid + i * 128;   // 512 float4 total
            const int kr  = idx >> 4;        // 0..31
            const int kc4 = (idx & 15) * 4;  // 0..60
            float4 kv = *(const float4*)(g_K + (bh * SS + kbase + kr) * HD + kc4);
            float4 vv = *(const float4*)(g_V + (bh * SS + kbase + kr) * HD + kc4);
            float4 ktf, vtf;
            ktf.x = tf2f(kv.x); ktf.y = tf2f(kv.y); ktf.z = tf2f(kv.z); ktf.w = tf2f(kv.w);
            vtf.x = tf2f(vv.x); vtf.y = tf2f(vv.y); vtf.z = tf2f(vv.z); vtf.w = tf2f(vv.w);
            *(float4*)&Ks[kr][kc4] = ktf;
            *(float4*)&Vs[kr][kc4] = vtf;
        }
        __syncthreads();
        const int skip = sflag;

        if (!skip) {
            // ---- scores: S = Q K^T  (64x32 per block, m16 x 4 n-tiles/warp) ----
            float s[4][4];
#pragma unroll
            for (int nt = 0; nt < 4; nt++)
#pragma unroll
                for (int i = 0; i < 4; i++) s[nt][i] = 0.f;
#pragma unroll
            for (int ks = 0; ks < 8; ks++) {
                const int kc = ks * 8;
#pragma unroll
                for (int nt = 0; nt < 4; nt++) {
                    const uint32_t b0 = __float_as_uint(Ks[nt * 8 + r][kc + c]);
                    const uint32_t b1 = __float_as_uint(Ks[nt * 8 + r][kc + c + 4]);
                    mma_tf32(s[nt], qf[ks], b0, b1);
                }
            }

            // ---- mask + online softmax ----
            float mloc_lo = -1e30f, mloc_hi = -1e30f;
#pragma unroll
            for (int nt = 0; nt < 4; nt++) {
                const int kc0 = nt * 8 + 2 * c;
                const float mk0 = msk[kc0], mk1 = msk[kc0 + 1];
                const int kg0 = kbase + kc0, kg1 = kg0 + 1;
                s[nt][0] = (kg0 > qg_lo) ? -1e30f : s[nt][0] + mk0;
                s[nt][1] = (kg1 > qg_lo) ? -1e30f : s[nt][1] + mk1;
                s[nt][2] = (kg0 > qg_hi) ? -1e30f : s[nt][2] + mk0;
                s[nt][3] = (kg1 > qg_hi) ? -1e30f : s[nt][3] + mk1;
                mloc_lo = fmaxf(mloc_lo, fmaxf(s[nt][0], s[nt][1]));
                mloc_hi = fmaxf(mloc_hi, fmaxf(s[nt][2], s[nt][3]));
            }
            mloc_lo = fmaxf(mloc_lo, __shfl_xor_sync(0xffffffffu, mloc_lo, 1));
            mloc_lo = fmaxf(mloc_lo, __shfl_xor_sync(0xffffffffu, mloc_lo, 2));
            mloc_hi = fmaxf(mloc_hi, __shfl_xor_sync(0xffffffffu, mloc_hi, 1));
            mloc_hi = fmaxf(mloc_hi, __shfl_xor_sync(0xffffffffu, mloc_hi, 2));

            const float mn_lo = fmaxf(m_lo, mloc_lo);
            const float mn_hi = fmaxf(m_hi, mloc_hi);
            const float a_lo = __expf(m_lo - mn_lo);
            const float a_hi = __expf(m_hi - mn_hi);
            m_lo = mn_lo; m_hi = mn_hi;

            float ps_lo = 0.f, ps_hi = 0.f;
            float p[4][4];
#pragma unroll
            for (int nt = 0; nt < 4; nt++) {
                p[nt][0] = __expf(s[nt][0] - mn_lo);
                p[nt][1] = __expf(s[nt][1] - mn_lo);
                p[nt][2] = __expf(s[nt][2] - mn_hi);
                p[nt][3] = __expf(s[nt][3] - mn_hi);
                ps_lo += p[nt][0] + p[nt][1];
                ps_hi += p[nt][2] + p[nt][3];
            }
            ps_lo += __shfl_xor_sync(0xffffffffu, ps_lo, 1);
            ps_lo += __shfl_xor_sync(0xffffffffu, ps_lo, 2);
            ps_hi += __shfl_xor_sync(0xffffffffu, ps_hi, 1);
            ps_hi += __shfl_xor_sync(0xffffffffu, ps_hi, 2);
            l_lo = a_lo * l_lo + ps_lo;
            l_hi = a_hi * l_hi + ps_hi;

#pragma unroll
            for (int nt = 0; nt < 8; nt++) {
                o[nt][0] *= a_lo; o[nt][1] *= a_lo;
                o[nt][2] *= a_hi; o[nt][3] *= a_hi;
            }

            // ---- P through per-warp-private smem (tf32-rounded) ----
#pragma unroll
            for (int nt = 0; nt < 4; nt++) {
                const int kc0 = nt * 8 + 2 * c;
                *(float2*)&Ps[qr + r    ][kc0] = make_float2(tf2f(p[nt][0]), tf2f(p[nt][1]));
                *(float2*)&Ps[qr + r + 8][kc0] = make_float2(tf2f(p[nt][2]), tf2f(p[nt][3]));
            }
            __syncwarp();

            // ---- O += P V  (m16 x 8 n-tiles, k = 32 keys = 4 ksteps) ----
#pragma unroll
            for (int ks = 0; ks < 4; ks++) {
                const int kc = ks * 8;
                uint32_t af[4];
                af[0] = __float_as_uint(Ps[qr + r    ][kc + c]);
                af[1] = __float_as_uint(Ps[qr + r + 8][kc + c]);
                af[2] = __float_as_uint(Ps[qr + r    ][kc + c + 4]);
                af[3] = __float_as_uint(Ps[qr + r + 8][kc + c + 4]);
#pragma unroll
                for (int nt = 0; nt < 8; nt++) {
                    const uint32_t b0 = __float_as_uint(Vs[kc + c    ][nt * 8 + r]);
                    const uint32_t b1 = __float_as_uint(Vs[kc + c + 4][nt * 8 + r]);
                    mma_tf32(o[nt], af, b0, b1);
                }
            }
        }
        __syncthreads();
    }

    // ---- epilogue: normalize + write to g_O (token-major, head offset) ----
    const float inv_lo = 1.f / l_lo;
    const float inv_hi = 1.f / l_hi;
    float* olo = g_O + (b_ * SS + qg_lo) * DD + h * HD;
    float* ohi = g_O + (b_ * SS + qg_hi) * DD + h * HD;
#pragma unroll
    for (int nt = 0; nt < 8; nt++) {
        const int dc = nt * 8 + 2 * c;
        *(float2*)&olo[dc] = make_float2(o[nt][0] * inv_lo, o[nt][1] * inv_lo);
        *(float2*)&ohi[dc] = make_float2(o[nt][2] * inv_hi, o[nt][3] * inv_hi);
    }
}

// ---------------------------------------------------------------------------
// Launch
// Inputs: 0:X 1:key_padding_mask 2:Wq 3:bq 4:Wk 5:bk 6:Wv 7:bv 8:Wo 9:bo
// ---------------------------------------------------------------------------
extern "C" void kernel_launch(void* const* d_in, const int* in_sizes, int n_in,
                              void* d_out, int out_size)
{
    const float* X   = (const float*)d_in[0];
    const int*   kpm = (const int*)  d_in[1];
    const float* Wq  = (const float*)d_in[2];
    const float* bq  = (const float*)d_in[3];
    const float* Wk  = (const float*)d_in[4];
    const float* bk  = (const float*)d_in[5];
    const float* Wv  = (const float*)d_in[6];
    const float* bv  = (const float*)d_in[7];
    const float* Wo  = (const float*)d_in[8];
    const float* bo  = (const float*)d_in[9];
    float* out = (float*)d_out;

    float *qptr, *kptr, *vptr;
    cudaGetSymbolAddress((void**)&qptr, g_Q);
    cudaGetSymbolAddress((void**)&kptr, g_K);
    cudaGetSymbolAddress((void**)&vptr, g_V);

    dim3 gproj(DD / 128, MTOK / 128);   // (8, 32)
    gemm_tf32<0><<<gproj, 256>>>(X, Wq, bq, qptr);
    gemm_tf32<0><<<gproj, 256>>>(X, Wk, bk, kptr);
    gemm_tf32<0><<<gproj, 256>>>(X, Wv, bv, vptr);

    dim3 gattn(SS / 64, BH);            // (32, 32)
    attn_tf32<<<gattn, 128>>>(kpm);

    gemm_tf32<1><<<gproj, 256>>>(nullptr, Wo, bo, out);
}

// round 4
// speedup vs baseline: 6.2140x; 1.0583x over previous
#include <cuda_runtime.h>
#include <math.h>
#include <float.h>
#include <stdint.h>

// Problem dims (fixed by the reference)
#define BB  2
#define SS  2048
#define DD  1024
#define HH  16
#define HD  64
#define BH  (BB*HH)          // 32
#define MTOK (BB*SS)         // 4096

// Scratch (device globals: allocation-free rule)
__device__ float g_Q[BH*SS*HD];   // [bh][s][hd]   (tf32-rounded)
__device__ float g_K[BH*SS*HD];   // (tf32-rounded)
__device__ float g_V[BH*SS*HD];   // (tf32-rounded)
__device__ float g_O[MTOK*DD];    // [b*S+s][d]    (tf32-rounded attn out)
__device__ float g_Xr[MTOK*DD];   // tf32-rounded X
__device__ float g_Wqr[DD*DD], g_Wkr[DD*DD], g_Wvr[DD*DD], g_Wor[DD*DD];

// ---------------------------------------------------------------------------
// Helpers
// ---------------------------------------------------------------------------
__device__ __forceinline__ uint32_t f2tf(float x) {
    uint32_t r;
    asm("cvt.rna.tf32.f32 %0, %1;" : "=r"(r) : "f"(x));
    return r;
}
__device__ __forceinline__ float tf2f(float x) {
    return __uint_as_float(f2tf(x));
}
__device__ __forceinline__ uint32_t smem_u32(const void* p) {
    uint32_t a;
    asm("{ .reg .u64 t; cvta.to.shared.u64 t, %1; cvt.u32.u64 %0, t; }" : "=r"(a) : "l"(p));
    return a;
}
__device__ __forceinline__ void cpa16(uint32_t dst, const void* src) {
    asm volatile("{ .reg .u64 g; cvta.to.global.u64 g, %1; cp.async.cg.shared.global [%0], [g], 16; }"
                 :: "r"(dst), "l"(src));
}
#define CPA_COMMIT() asm volatile("cp.async.commit_group;" ::: "memory")
#define CPA_WAIT0()  asm volatile("cp.async.wait_group 0;" ::: "memory")
#define CPA_WAIT1()  asm volatile("cp.async.wait_group 1;" ::: "memory")

// D += A * B  (m16n8k8 mma.sync, tf32 inputs, f32 accum)
__device__ __forceinline__ void mma_tf32(float* d, const uint32_t* a, uint32_t b0, uint32_t b1) {
    asm volatile(
        "mma.sync.aligned.m16n8k8.row.col.f32.tf32.tf32.f32 "
        "{%0,%1,%2,%3},{%4,%5,%6,%7},{%8,%9},{%0,%1,%2,%3};"
        : "+f"(d[0]), "+f"(d[1]), "+f"(d[2]), "+f"(d[3])
        : "r"(a[0]), "r"(a[1]), "r"(a[2]), "r"(a[3]), "r"(b0), "r"(b1));
}

// ---------------------------------------------------------------------------
// Prepass: tf32-round a tensor (float4 granularity)
// ---------------------------------------------------------------------------
__global__ void round_k(float* __restrict__ dst, const float* __restrict__ src, int n4)
{
    const int i = blockIdx.x * blockDim.x + threadIdx.x;
    if (i < n4) {
        float4 v = ((const float4*)src)[i];
        v.x = tf2f(v.x); v.y = tf2f(v.y); v.z = tf2f(v.z); v.w = tf2f(v.w);
        ((float4*)dst)[i] = v;
    }
}

// ---------------------------------------------------------------------------
// TF32 mma.sync NT GEMM, 2-stage cp.async pipeline.
// C[m][n] = sum_k A[m][k]*W[n][k] + bias[n].  Inputs pre-rounded to tf32.
// Block 128x128, k-chunk 32, 256 threads = 8 warps (4m x 2n), warp tile 32x64.
// Smem per stage: As[128][36] + Bs[128][36] (pad 36 -> conflict-free frags,
// rows 144B = 16B-aligned for cp.async).
// MODE 0: scatter head-major (rounded) into Cout=[bh][s][hd]
// MODE 1: A=g_O, row-major fp32 into Cout (final output)
// ---------------------------------------------------------------------------
#define GST  18432u                    // one matrix: 128*36*4
#define GSTG 36864u                    // one stage: A + B
#define GSM_TOTAL (2 * 36864)

template<int MODE>
__global__ __launch_bounds__(256, 2)
void gemm_tf32(const float* __restrict__ Ain,
               const float* __restrict__ W,
               const float* __restrict__ bias,
               float* __restrict__ Cout)
{
    extern __shared__ char smem[];
    const uint32_t sb = smem_u32(smem);
    const float* A = (MODE == 1) ? (const float*)g_O : Ain;

    const int m0 = blockIdx.y * 128;
    const int n0 = blockIdx.x * 128;
    const int tid  = threadIdx.x;
    const int warp = tid >> 5;
    const int lane = tid & 31;
    const int r = lane >> 2;
    const int c = lane & 3;
    const int wm = (warp & 3) * 32;
    const int wn = (warp >> 2) * 64;

    float acc[2][8][4];
#pragma unroll
    for (int mt = 0; mt < 2; mt++)
#pragma unroll
        for (int nt = 0; nt < 8; nt++)
#pragma unroll
            for (int i = 0; i < 4; i++) acc[mt][nt][i] = 0.f;

    // fill stage st with k-chunk [k0, k0+32)
    auto fill = [&](int st, int k0) {
        const uint32_t base = sb + (uint32_t)st * GSTG;
#pragma unroll
        for (int t = 0; t < 4; t++) {
            const int idx = tid + t * 256;        // 0..1023
            const int row = idx >> 3;             // 0..127
            const int cf  = (idx & 7) * 4;        // float col 0..28
            const uint32_t so = (uint32_t)(row * 144 + cf * 4);
            cpa16(base + so,        A + (size_t)(m0 + row) * DD + k0 + cf);
            cpa16(base + GST + so,  W + (size_t)(n0 + row) * DD + k0 + cf);
        }
        CPA_COMMIT();
    };

    fill(0, 0);

    for (int i = 0; i < 32; i++) {
        const int st = i & 1;
        CPA_WAIT0();
        __syncthreads();
        if (i + 1 < 32) fill((i + 1) & 1, (i + 1) * 32);

        float (*As)[36] = (float(*)[36])(smem + st * GSTG);
        float (*Bs)[36] = (float(*)[36])(smem + st * GSTG + GST);

#pragma unroll
        for (int ks = 0; ks < 4; ks++) {
            const int kc = ks * 8;
            uint32_t bf[8][2];
#pragma unroll
            for (int nt = 0; nt < 8; nt++) {
                bf[nt][0] = __float_as_uint(Bs[wn + nt * 8 + r][kc + c]);
                bf[nt][1] = __float_as_uint(Bs[wn + nt * 8 + r][kc + c + 4]);
            }
            uint32_t af[2][4];
#pragma unroll
            for (int mt = 0; mt < 2; mt++) {
                const int mr = wm + mt * 16 + r;
                af[mt][0] = __float_as_uint(As[mr    ][kc + c]);
                af[mt][1] = __float_as_uint(As[mr + 8][kc + c]);
                af[mt][2] = __float_as_uint(As[mr    ][kc + c + 4]);
                af[mt][3] = __float_as_uint(As[mr + 8][kc + c + 4]);
            }
#pragma unroll
            for (int mt = 0; mt < 2; mt++)
#pragma unroll
                for (int nt = 0; nt < 8; nt++)
                    mma_tf32(acc[mt][nt], af[mt], bf[nt][0], bf[nt][1]);
        }
    }

    // Epilogue
#pragma unroll
    for (int mt = 0; mt < 2; mt++) {
        const int m_lo = m0 + wm + mt * 16 + r;
        const int m_hi = m_lo + 8;
#pragma unroll
        for (int nt = 0; nt < 8; nt++) {
            const int n = n0 + wn + nt * 8 + 2 * c;
            const float b0 = bias[n], b1 = bias[n + 1];
            float2 lo, hi;
            if (MODE == 0) {   // rounded: feeds attention tensor cores
                lo = make_float2(tf2f(acc[mt][nt][0] + b0), tf2f(acc[mt][nt][1] + b1));
                hi = make_float2(tf2f(acc[mt][nt][2] + b0), tf2f(acc[mt][nt][3] + b1));
                const int h  = n >> 6;
                const int hd = n & 63;
                const int blo = m_lo >> 11, slo = m_lo & 2047;
                const int bhi = m_hi >> 11, shi = m_hi & 2047;
                *(float2*)&Cout[(((size_t)(blo * HH + h) * SS) + slo) * HD + hd] = lo;
                *(float2*)&Cout[(((size_t)(bhi * HH + h) * SS) + shi) * HD + hd] = hi;
            } else {           // final output: exact fp32
                lo = make_float2(acc[mt][nt][0] + b0, acc[mt][nt][1] + b1);
                hi = make_float2(acc[mt][nt][2] + b0, acc[mt][nt][3] + b1);
                *(float2*)&Cout[(size_t)m_lo * DD + n] = lo;
                *(float2*)&Cout[(size_t)m_hi * DD + n] = hi;
            }
        }
    }
}

// ---------------------------------------------------------------------------
// Flash attention, tf32 mma.sync, 3-stage cp.async K/V/mask pipeline.
// Block: 64 q rows of one (b,h), 128 threads = 4 warps.
// Stage layout (bytes): K[32][68] @0 (8704), V[32][72] @8704 (9216),
// mask[32] @17920 (128) -> stage=18432.  3 stages, then Ps[64][36] @55296.
// ---------------------------------------------------------------------------
#define AKOFF 0u
#define AVOFF 8704u
#define AMOFF 17920u
#define ASTG  18432u
#define APOFF 55296u
#define ASM_TOTAL (55296 + 64*36*4)     // 64512

__global__ __launch_bounds__(128, 3)
void attn_tf32(const int* __restrict__ kpm)
{
    extern __shared__ char smem[];
    const uint32_t sb = smem_u32(smem);

    const int qt = gridDim.x - 1 - blockIdx.x;   // heavy causal blocks first
    const int bh = blockIdx.y;
    const int b_ = bh >> 4;
    const int h  = bh & 15;
    const int tid  = threadIdx.x;
    const int warp = tid >> 5;
    const int lane = tid & 31;
    const int r = lane >> 2;
    const int c = lane & 3;
    const int q0 = qt * 64;
    const int qr = warp * 16;
    const int qg_lo = q0 + qr + r;
    const int qg_hi = qg_lo + 8;

    // fill stage st with key tile kt (K, V, mask) — pure cp.async
    auto fill = [&](int st, int kt) {
        const int kbase = kt * 32;
        const uint32_t base = sb + (uint32_t)st * ASTG;
#pragma unroll
        for (int i = 0; i < 4; i++) {
            const int idx = tid + i * 128;   // 0..511
            const int kr  = idx >> 4;        // 0..31
            const int cf  = (idx & 15) * 4;  // 0..60
            cpa16(base + AKOFF + (uint32_t)(kr * 272 + cf * 4),
                  g_K + (size_t)(bh * SS + kbase + kr) * HD + cf);
            cpa16(base + AVOFF + (uint32_t)(kr * 288 + cf * 4),
                  g_V + (size_t)(bh * SS + kbase + kr) * HD + cf);
        }
        if (tid < 8)
            cpa16(base + AMOFF + tid * 16, kpm + (size_t)b_ * SS + kbase + tid * 4);
        CPA_COMMIT();
    };

    // Q fragments (pre-rounded tf32 in g_Q; *0.125f is exact)
    uint32_t qf[8][4];
    {
        const float* qlo = g_Q + (size_t)(bh * SS + qg_lo) * HD;
        const float* qhi = g_Q + (size_t)(bh * SS + qg_hi) * HD;
#pragma unroll
        for (int ks = 0; ks < 8; ks++) {
            qf[ks][0] = __float_as_uint(qlo[ks * 8 + c]     * 0.125f);
            qf[ks][1] = __float_as_uint(qhi[ks * 8 + c]     * 0.125f);
            qf[ks][2] = __float_as_uint(qlo[ks * 8 + c + 4] * 0.125f);
            qf[ks][3] = __float_as_uint(qhi[ks * 8 + c + 4] * 0.125f);
        }
    }

    float o[8][4];
#pragma unroll
    for (int nt = 0; nt < 8; nt++)
#pragma unroll
        for (int i = 0; i < 4; i++) o[nt][i] = 0.f;
    float m_lo = -1e30f, m_hi = -1e30f, l_lo = 0.f, l_hi = 0.f;

    const int kt_max = 2 * qt + 1;   // >= 1 always
    fill(0, 0);
    fill(1, 1);

    int st = 0, st2 = 2;             // st = kt%3, st2 = (kt+2)%3
    for (int kt = 0; kt <= kt_max; kt++) {
        if (kt + 1 <= kt_max) { CPA_WAIT1(); } else { CPA_WAIT0(); }
        __syncthreads();
        if (kt + 2 <= kt_max) fill(st2, kt + 2);

        const uint32_t base = (uint32_t)st * ASTG;
        float (*Ks)[68] = (float(*)[68])(smem + base + AKOFF);
        float (*Vs)[72] = (float(*)[72])(smem + base + AVOFF);
        const int* mk   = (const int*)  (smem + base + AMOFF);
        float (*Ps)[36] = (float(*)[36])(smem + APOFF);

        const int kbase = kt * 32;
        const int mymask = mk[lane];
        const int skip = __all_sync(0xffffffffu, mymask != 0);

        if (!skip) {
            // ---- scores: S = Q K^T ----
            float s[4][4];
#pragma unroll
            for (int nt = 0; nt < 4; nt++)
#pragma unroll
                for (int i = 0; i < 4; i++) s[nt][i] = 0.f;
#pragma unroll
            for (int ks = 0; ks < 8; ks++) {
                const int kc = ks * 8;
#pragma unroll
                for (int nt = 0; nt < 4; nt++) {
                    const uint32_t b0 = __float_as_uint(Ks[nt * 8 + r][kc + c]);
                    const uint32_t b1 = __float_as_uint(Ks[nt * 8 + r][kc + c + 4]);
                    mma_tf32(s[nt], qf[ks], b0, b1);
                }
            }

            // ---- mask + online softmax ----
            float mloc_lo = -1e30f, mloc_hi = -1e30f;
#pragma unroll
            for (int nt = 0; nt < 4; nt++) {
                const int kc0 = nt * 8 + 2 * c;
                const bool bad0 = mk[kc0] != 0;
                const bool bad1 = mk[kc0 + 1] != 0;
                const int kg0 = kbase + kc0, kg1 = kg0 + 1;
                s[nt][0] = (bad0 || kg0 > qg_lo) ? -1e30f : s[nt][0];
                s[nt][1] = (bad1 || kg1 > qg_lo) ? -1e30f : s[nt][1];
                s[nt][2] = (bad0 || kg0 > qg_hi) ? -1e30f : s[nt][2];
                s[nt][3] = (bad1 || kg1 > qg_hi) ? -1e30f : s[nt][3];
                mloc_lo = fmaxf(mloc_lo, fmaxf(s[nt][0], s[nt][1]));
                mloc_hi = fmaxf(mloc_hi, fmaxf(s[nt][2], s[nt][3]));
            }
            mloc_lo = fmaxf(mloc_lo, __shfl_xor_sync(0xffffffffu, mloc_lo, 1));
            mloc_lo = fmaxf(mloc_lo, __shfl_xor_sync(0xffffffffu, mloc_lo, 2));
            mloc_hi = fmaxf(mloc_hi, __shfl_xor_sync(0xffffffffu, mloc_hi, 1));
            mloc_hi = fmaxf(mloc_hi, __shfl_xor_sync(0xffffffffu, mloc_hi, 2));

            const float mn_lo = fmaxf(m_lo, mloc_lo);
            const float mn_hi = fmaxf(m_hi, mloc_hi);
            const float a_lo = __expf(m_lo - mn_lo);
            const float a_hi = __expf(m_hi - mn_hi);
            m_lo = mn_lo; m_hi = mn_hi;

            float ps_lo = 0.f, ps_hi = 0.f;
            float p[4][4];
#pragma unroll
            for (int nt = 0; nt < 4; nt++) {
                p[nt][0] = __expf(s[nt][0] - mn_lo);
                p[nt][1] = __expf(s[nt][1] - mn_lo);
                p[nt][2] = __expf(s[nt][2] - mn_hi);
                p[nt][3] = __expf(s[nt][3] - mn_hi);
                ps_lo += p[nt][0] + p[nt][1];
                ps_hi += p[nt][2] + p[nt][3];
            }
            ps_lo += __shfl_xor_sync(0xffffffffu, ps_lo, 1);
            ps_lo += __shfl_xor_sync(0xffffffffu, ps_lo, 2);
            ps_hi += __shfl_xor_sync(0xffffffffu, ps_hi, 1);
            ps_hi += __shfl_xor_sync(0xffffffffu, ps_hi, 2);
            l_lo = a_lo * l_lo + ps_lo;
            l_hi = a_hi * l_hi + ps_hi;

#pragma unroll
            for (int nt = 0; nt < 8; nt++) {
                o[nt][0] *= a_lo; o[nt][1] *= a_lo;
                o[nt][2] *= a_hi; o[nt][3] *= a_hi;
            }

            // ---- P through per-warp-private smem (tf32-rounded) ----
#pragma unroll
            for (int nt = 0; nt < 4; nt++) {
                const int kc0 = nt * 8 + 2 * c;
                *(float2*)&Ps[qr + r    ][kc0] = make_float2(tf2f(p[nt][0]), tf2f(p[nt][1]));
                *(float2*)&Ps[qr + r + 8][kc0] = make_float2(tf2f(p[nt][2]), tf2f(p[nt][3]));
            }
            __syncwarp();

            // ---- O += P V ----
#pragma unroll
            for (int ks = 0; ks < 4; ks++) {
                const int kc = ks * 8;
                uint32_t af[4];
                af[0] = __float_as_uint(Ps[qr + r    ][kc + c]);
                af[1] = __float_as_uint(Ps[qr + r + 8][kc + c]);
                af[2] = __float_as_uint(Ps[qr + r    ][kc + c + 4]);
                af[3] = __float_as_uint(Ps[qr + r + 8][kc + c + 4]);
#pragma unroll
                for (int nt = 0; nt < 8; nt++) {
                    const uint32_t b0 = __float_as_uint(Vs[kc + c    ][nt * 8 + r]);
                    const uint32_t b1 = __float_as_uint(Vs[kc + c + 4][nt * 8 + r]);
                    mma_tf32(o[nt], af, b0, b1);
                }
            }
        }

        st  = (st  == 2) ? 0 : st  + 1;
        st2 = (st2 == 2) ? 0 : st2 + 1;
    }

    // ---- epilogue: normalize, round (feeds out-proj tensor cores), store ----
    const float inv_lo = 1.f / l_lo;
    const float inv_hi = 1.f / l_hi;
    float* olo = g_O + (size_t)(b_ * SS + qg_lo) * DD + h * HD;
    float* ohi = g_O + (size_t)(b_ * SS + qg_hi) * DD + h * HD;
#pragma unroll
    for (int nt = 0; nt < 8; nt++) {
        const int dc = nt * 8 + 2 * c;
        *(float2*)&olo[dc] = make_float2(tf2f(o[nt][0] * inv_lo), tf2f(o[nt][1] * inv_lo));
        *(float2*)&ohi[dc] = make_float2(tf2f(o[nt][2] * inv_hi), tf2f(o[nt][3] * inv_hi));
    }
}

// ---------------------------------------------------------------------------
// Launch
// Inputs: 0:X 1:key_padding_mask 2:Wq 3:bq 4:Wk 5:bk 6:Wv 7:bv 8:Wo 9:bo
// ---------------------------------------------------------------------------
extern "C" void kernel_launch(void* const* d_in, const int* in_sizes, int n_in,
                              void* d_out, int out_size)
{
    const float* X   = (const float*)d_in[0];
    const int*   kpm = (const int*)  d_in[1];
    const float* Wq  = (const float*)d_in[2];
    const float* bq  = (const float*)d_in[3];
    const float* Wk  = (const float*)d_in[4];
    const float* bk  = (const float*)d_in[5];
    const float* Wv  = (const float*)d_in[6];
    const float* bv  = (const float*)d_in[7];
    const float* Wo  = (const float*)d_in[8];
    const float* bo  = (const float*)d_in[9];
    float* out = (float*)d_out;

    float *qp, *kp, *vp, *xr, *wqr, *wkr, *wvr, *wor;
    cudaGetSymbolAddress((void**)&qp,  g_Q);
    cudaGetSymbolAddress((void**)&kp,  g_K);
    cudaGetSymbolAddress((void**)&vp,  g_V);
    cudaGetSymbolAddress((void**)&xr,  g_Xr);
    cudaGetSymbolAddress((void**)&wqr, g_Wqr);
    cudaGetSymbolAddress((void**)&wkr, g_Wkr);
    cudaGetSymbolAddress((void**)&wvr, g_Wvr);
    cudaGetSymbolAddress((void**)&wor, g_Wor);

    cudaFuncSetAttribute(gemm_tf32<0>, cudaFuncAttributeMaxDynamicSharedMemorySize, GSM_TOTAL);
    cudaFuncSetAttribute(gemm_tf32<1>, cudaFuncAttributeMaxDynamicSharedMemorySize, GSM_TOTAL);
    cudaFuncSetAttribute(attn_tf32,    cudaFuncAttributeMaxDynamicSharedMemorySize, ASM_TOTAL);

    // Prepass: tf32-round X and weights
    round_k<<<(MTOK*DD/4 + 255)/256, 256>>>(xr,  X,  MTOK*DD/4);
    round_k<<<(DD*DD/4  + 255)/256, 256>>>(wqr, Wq, DD*DD/4);
    round_k<<<(DD*DD/4  + 255)/256, 256>>>(wkr, Wk, DD*DD/4);
    round_k<<<(DD*DD/4  + 255)/256, 256>>>(wvr, Wv, DD*DD/4);
    round_k<<<(DD*DD/4  + 255)/256, 256>>>(wor, Wo, DD*DD/4);

    dim3 gproj(DD / 128, MTOK / 128);   // (8, 32)
    gemm_tf32<0><<<gproj, 256, GSM_TOTAL>>>(xr, wqr, bq, qp);
    gemm_tf32<0><<<gproj, 256, GSM_TOTAL>>>(xr, wkr, bk, kp);
    gemm_tf32<0><<<gproj, 256, GSM_TOTAL>>>(xr, wvr, bv, vp);

    dim3 gattn(SS / 64, BH);            // (32, 32)
    attn_tf32<<<gattn, 128, ASM_TOTAL>>>(kpm);

    gemm_tf32<1><<<gproj, 256, GSM_TOTAL>>>(nullptr, wor, bo, out);
}

// round 5
// speedup vs baseline: 6.5163x; 1.0487x over previous
#include <cuda_runtime.h>
#include <math.h>
#include <float.h>
#include <stdint.h>

// Problem dims (fixed by the reference)
#define BB  2
#define SS  2048
#define DD  1024
#define HH  16
#define HD  64
#define BH  (BB*HH)          // 32
#define MTOK (BB*SS)         // 4096

// Scratch (device globals: allocation-free rule)
__device__ float g_Q[BH*SS*HD];   // [bh][s][hd]   (tf32-rounded)
__device__ float g_K[BH*SS*HD];
__device__ float g_V[BH*SS*HD];
__device__ float g_O[MTOK*DD];    // [b*S+s][d]    (tf32-rounded attn out)
__device__ float g_Wqr[DD*DD], g_Wkr[DD*DD], g_Wvr[DD*DD], g_Wor[DD*DD];

// ---------------------------------------------------------------------------
// Helpers
// ---------------------------------------------------------------------------
__device__ __forceinline__ uint32_t f2tf(float x) {
    uint32_t r;
    asm("cvt.rna.tf32.f32 %0, %1;" : "=r"(r) : "f"(x));
    return r;
}
__device__ __forceinline__ float tf2f(float x) {
    return __uint_as_float(f2tf(x));
}
__device__ __forceinline__ uint32_t smem_u32(const void* p) {
    uint32_t a;
    asm("{ .reg .u64 t; cvta.to.shared.u64 t, %1; cvt.u32.u64 %0, t; }" : "=r"(a) : "l"(p));
    return a;
}
__device__ __forceinline__ void cpa16(uint32_t dst, const void* src) {
    asm volatile("{ .reg .u64 g; cvta.to.global.u64 g, %1; cp.async.cg.shared.global [%0], [g], 16; }"
                 :: "r"(dst), "l"(src));
}
#define CPA_COMMIT() asm volatile("cp.async.commit_group;" ::: "memory")
#define CPA_WAIT0()  asm volatile("cp.async.wait_group 0;" ::: "memory")

// D += A * B  (m16n8k8 mma.sync, tf32 inputs, f32 accum)
__device__ __forceinline__ void mma_tf32(float* d, const uint32_t* a, uint32_t b0, uint32_t b1) {
    asm volatile(
        "mma.sync.aligned.m16n8k8.row.col.f32.tf32.tf32.f32 "
        "{%0,%1,%2,%3},{%4,%5,%6,%7},{%8,%9},{%0,%1,%2,%3};"
        : "+f"(d[0]), "+f"(d[1]), "+f"(d[2]), "+f"(d[3])
        : "r"(a[0]), "r"(a[1]), "r"(a[2]), "r"(a[3]), "r"(b0), "r"(b1));
}

// ---------------------------------------------------------------------------
// Prepass: tf32-round the 4 weight matrices in ONE launch.
// ---------------------------------------------------------------------------
#define WQUAD (DD*DD/4)        // 262144 float4 per matrix
__global__ void round_w(const float* __restrict__ wq, const float* __restrict__ wk,
                        const float* __restrict__ wv, const float* __restrict__ wo,
                        float* __restrict__ oq, float* __restrict__ ok,
                        float* __restrict__ ov, float* __restrict__ oo)
{
    const int i   = blockIdx.x * blockDim.x + threadIdx.x;  // 0..4*WQUAD-1
    const int reg = i >> 18;
    const int loc = i & (WQUAD - 1);
    const float* s = (reg == 0) ? wq : (reg == 1) ? wk : (reg == 2) ? wv : wo;
    float*       d = (reg == 0) ? oq : (reg == 1) ? ok : (reg == 2) ? ov : oo;
    float4 v = ((const float4*)s)[loc];
    v.x = tf2f(v.x); v.y = tf2f(v.y); v.z = tf2f(v.z); v.w = tf2f(v.w);
    ((float4*)d)[loc] = v;
}

// ---------------------------------------------------------------------------
// GEMM core (tf32 mma.sync, 2-stage cp.async, block 128x128, k-chunk 32,
// 256 thr = 8 warps (4m x 2n), warp tile 32x64).
// CVT_A: tf32-round A fragments in-register (A staged raw).
// B (weights) must be pre-rounded.
// ---------------------------------------------------------------------------
#define GST  18432u                    // one matrix: 128*36*4
#define GSTG 36864u                    // one stage: A + B
#define GSM_TOTAL (2 * 36864)

template<int CVT_A, int HEADOUT>
__device__ __forceinline__ void gemm_body(
    const float* __restrict__ A, const float* __restrict__ W,
    const float* __restrict__ bias, float* __restrict__ Cout,
    int m0, int n0, char* smem)
{
    const uint32_t sb = smem_u32(smem);
    const int tid  = threadIdx.x;
    const int warp = tid >> 5;
    const int lane = tid & 31;
    const int r = lane >> 2;
    const int c = lane & 3;
    const int wm = (warp & 3) * 32;
    const int wn = (warp >> 2) * 64;

    float acc[2][8][4];
#pragma unroll
    for (int mt = 0; mt < 2; mt++)
#pragma unroll
        for (int nt = 0; nt < 8; nt++)
#pragma unroll
            for (int i = 0; i < 4; i++) acc[mt][nt][i] = 0.f;

    auto fill = [&](int st, int k0) {
        const uint32_t base = sb + (uint32_t)st * GSTG;
#pragma unroll
        for (int t = 0; t < 4; t++) {
            const int idx = tid + t * 256;
            const int row = idx >> 3;
            const int cf  = (idx & 7) * 4;
            const uint32_t so = (uint32_t)(row * 144 + cf * 4);
            cpa16(base + so,       A + (size_t)(m0 + row) * DD + k0 + cf);
            cpa16(base + GST + so, W + (size_t)(n0 + row) * DD + k0 + cf);
        }
        CPA_COMMIT();
    };

    fill(0, 0);

    for (int i = 0; i < 32; i++) {
        const int st = i & 1;
        CPA_WAIT0();
        __syncthreads();
        if (i + 1 < 32) fill((i + 1) & 1, (i + 1) * 32);

        float (*As)[36] = (float(*)[36])(smem + st * GSTG);
        float (*Bs)[36] = (float(*)[36])(smem + st * GSTG + GST);

#pragma unroll
        for (int ks = 0; ks < 4; ks++) {
            const int kc = ks * 8;
            uint32_t bf[8][2];
#pragma unroll
            for (int nt = 0; nt < 8; nt++) {
                bf[nt][0] = __float_as_uint(Bs[wn + nt * 8 + r][kc + c]);
                bf[nt][1] = __float_as_uint(Bs[wn + nt * 8 + r][kc + c + 4]);
            }
            uint32_t af[2][4];
#pragma unroll
            for (int mt = 0; mt < 2; mt++) {
                const int mr = wm + mt * 16 + r;
                if (CVT_A) {
                    af[mt][0] = f2tf(As[mr    ][kc + c]);
                    af[mt][1] = f2tf(As[mr + 8][kc + c]);
                    af[mt][2] = f2tf(As[mr    ][kc + c + 4]);
                    af[mt][3] = f2tf(As[mr + 8][kc + c + 4]);
                } else {
                    af[mt][0] = __float_as_uint(As[mr    ][kc + c]);
                    af[mt][1] = __float_as_uint(As[mr + 8][kc + c]);
                    af[mt][2] = __float_as_uint(As[mr    ][kc + c + 4]);
                    af[mt][3] = __float_as_uint(As[mr + 8][kc + c + 4]);
                }
            }
#pragma unroll
            for (int mt = 0; mt < 2; mt++)
#pragma unroll
                for (int nt = 0; nt < 8; nt++)
                    mma_tf32(acc[mt][nt], af[mt], bf[nt][0], bf[nt][1]);
        }
    }

#pragma unroll
    for (int mt = 0; mt < 2; mt++) {
        const int m_lo = m0 + wm + mt * 16 + r;
        const int m_hi = m_lo + 8;
#pragma unroll
        for (int nt = 0; nt < 8; nt++) {
            const int n = wn + nt * 8 + 2 * c;   // local n within [0,128)
            const int ng = n0 + n;               // within this matrix's 1024
            const float b0 = bias[ng], b1 = bias[ng + 1];
            if (HEADOUT) {   // rounded, head-major scatter
                float2 lo = make_float2(tf2f(acc[mt][nt][0] + b0), tf2f(acc[mt][nt][1] + b1));
                float2 hi = make_float2(tf2f(acc[mt][nt][2] + b0), tf2f(acc[mt][nt][3] + b1));
                const int h  = ng >> 6;
                const int hd = ng & 63;
                const int blo = m_lo >> 11, slo = m_lo & 2047;
                const int bhi = m_hi >> 11, shi = m_hi & 2047;
                *(float2*)&Cout[(((size_t)(blo * HH + h) * SS) + slo) * HD + hd] = lo;
                *(float2*)&Cout[(((size_t)(bhi * HH + h) * SS) + shi) * HD + hd] = hi;
            } else {         // exact fp32, row-major (final output)
                *(float2*)&Cout[(size_t)m_lo * DD + ng] = make_float2(acc[mt][nt][0] + b0, acc[mt][nt][1] + b1);
                *(float2*)&Cout[(size_t)m_hi * DD + ng] = make_float2(acc[mt][nt][2] + b0, acc[mt][nt][3] + b1);
            }
        }
    }
}

// Fused QKV: grid (24, 32); virtual n picks matrix.
__global__ __launch_bounds__(256, 2)
void gemm_qkv(const float* __restrict__ X,
              const float* __restrict__ wq, const float* __restrict__ wk, const float* __restrict__ wv,
              const float* __restrict__ bq, const float* __restrict__ bk, const float* __restrict__ bv,
              float* __restrict__ Qo, float* __restrict__ Ko, float* __restrict__ Vo)
{
    extern __shared__ char smem[];
    const int n0v   = blockIdx.x * 128;          // 0..2944
    const int which = n0v >> 10;
    const int n0    = n0v & 1023;
    const float* W    = (which == 0) ? wq : (which == 1) ? wk : wv;
    const float* bias = (which == 0) ? bq : (which == 1) ? bk : bv;
    float*       Out  = (which == 0) ? Qo : (which == 1) ? Ko : Vo;
    gemm_body<1, 1>(X, W, bias, Out, blockIdx.y * 128, n0, smem);
}

// Output projection: A = g_O (pre-rounded), exact fp32 out.
__global__ __launch_bounds__(256, 2)
void gemm_out(const float* __restrict__ wo, const float* __restrict__ bo,
              float* __restrict__ Cout)
{
    extern __shared__ char smem[];
    gemm_body<0, 0>((const float*)g_O, wo, bo, Cout, blockIdx.y * 128, blockIdx.x * 128, smem);
}

// ---------------------------------------------------------------------------
// Flash attention, tf32 mma.sync, 64-key tiles, 2-stage cp.async,
// shuffle-based P re-fragmentation (no Ps smem, no syncwarp).
// Block: 64 q rows of one (b,h), 128 threads = 4 warps x 16 q rows.
// Stage: K[64][68] @0 (17408), V[64][72] @17408 (18432), mask[64] @35840 (256)
// ---------------------------------------------------------------------------
#define AKOFF 0u
#define AVOFF 17408u
#define AMOFF 35840u
#define ASTG  36096u
#define ASM_TOTAL (2 * 36096)     // 72192

__global__ __launch_bounds__(128, 3)
void attn_tf32(const int* __restrict__ kpm)
{
    extern __shared__ char smem[];
    const uint32_t sb = smem_u32(smem);

    const int qt = gridDim.x - 1 - blockIdx.x;   // heavy causal blocks first
    const int bh = blockIdx.y;
    const int b_ = bh >> 4;
    const int h  = bh & 15;
    const int tid  = threadIdx.x;
    const int warp = tid >> 5;
    const int lane = tid & 31;
    const int r = lane >> 2;
    const int c = lane & 3;
    const int q0 = qt * 64;
    const int qg_lo = q0 + warp * 16 + r;
    const int qg_hi = qg_lo + 8;

    auto fill = [&](int st, int kt) {
        const int kbase = kt * 64;
        const uint32_t base = sb + (uint32_t)st * ASTG;
#pragma unroll
        for (int i = 0; i < 8; i++) {
            const int idx = tid + i * 128;   // 0..1023
            const int kr  = idx >> 4;        // 0..63
            const int cf  = (idx & 15) * 4;  // 0..60
            cpa16(base + AKOFF + (uint32_t)(kr * 272 + cf * 4),
                  g_K + (size_t)(bh * SS + kbase + kr) * HD + cf);
            cpa16(base + AVOFF + (uint32_t)(kr * 288 + cf * 4),
                  g_V + (size_t)(bh * SS + kbase + kr) * HD + cf);
        }
        if (tid < 16)
            cpa16(base + AMOFF + tid * 16, kpm + (size_t)b_ * SS + kbase + tid * 4);
        CPA_COMMIT();
    };

    // Q fragments (g_Q is tf32-clean; *0.125f exact)
    uint32_t qf[8][4];
    {
        const float* qlo = g_Q + (size_t)(bh * SS + qg_lo) * HD;
        const float* qhi = g_Q + (size_t)(bh * SS + qg_hi) * HD;
#pragma unroll
        for (int ks = 0; ks < 8; ks++) {
            qf[ks][0] = __float_as_uint(qlo[ks * 8 + c]     * 0.125f);
            qf[ks][1] = __float_as_uint(qhi[ks * 8 + c]     * 0.125f);
            qf[ks][2] = __float_as_uint(qlo[ks * 8 + c + 4] * 0.125f);
            qf[ks][3] = __float_as_uint(qhi[ks * 8 + c + 4] * 0.125f);
        }
    }

    float o[8][4];
#pragma unroll
    for (int nt = 0; nt < 8; nt++)
#pragma unroll
        for (int i = 0; i < 4; i++) o[nt][i] = 0.f;
    float m_lo = -1e30f, m_hi = -1e30f, l_lo = 0.f, l_hi = 0.f;

    const int kt_max = qt;
    fill(0, 0);

    for (int kt = 0; kt <= kt_max; kt++) {
        CPA_WAIT0();
        __syncthreads();
        if (kt + 1 <= kt_max) fill((kt + 1) & 1, kt + 1);

        const uint32_t base = (uint32_t)(kt & 1) * ASTG;
        float (*Ks)[68] = (float(*)[68])(smem + base + AKOFF);
        float (*Vs)[72] = (float(*)[72])(smem + base + AVOFF);
        const int* mk   = (const int*)  (smem + base + AMOFF);

        const int kbase = kt * 64;
        const int skip = __all_sync(0xffffffffu, (mk[lane] != 0) && (mk[lane + 32] != 0));

        if (!skip) {
            // ---- scores: S = Q K^T  (16 rows x 64 keys per warp) ----
            float s[8][4];
#pragma unroll
            for (int nt = 0; nt < 8; nt++)
#pragma unroll
                for (int i = 0; i < 4; i++) s[nt][i] = 0.f;
#pragma unroll
            for (int ks = 0; ks < 8; ks++) {
                const int kc = ks * 8;
#pragma unroll
                for (int nt = 0; nt < 8; nt++) {
                    const uint32_t b0 = __float_as_uint(Ks[nt * 8 + r][kc + c]);
                    const uint32_t b1 = __float_as_uint(Ks[nt * 8 + r][kc + c + 4]);
                    mma_tf32(s[nt], qf[ks], b0, b1);
                }
            }

            // ---- mask + online softmax ----
            float mloc_lo = -1e30f, mloc_hi = -1e30f;
#pragma unroll
            for (int nt = 0; nt < 8; nt++) {
                const int kc0 = nt * 8 + 2 * c;
                const bool bad0 = mk[kc0] != 0;
                const bool bad1 = mk[kc0 + 1] != 0;
                const int kg0 = kbase + kc0, kg1 = kg0 + 1;
                s[nt][0] = (bad0 || kg0 > qg_lo) ? -1e30f : s[nt][0];
                s[nt][1] = (bad1 || kg1 > qg_lo) ? -1e30f : s[nt][1];
                s[nt][2] = (bad0 || kg0 > qg_hi) ? -1e30f : s[nt][2];
                s[nt][3] = (bad1 || kg1 > qg_hi) ? -1e30f : s[nt][3];
                mloc_lo = fmaxf(mloc_lo, fmaxf(s[nt][0], s[nt][1]));
                mloc_hi = fmaxf(mloc_hi, fmaxf(s[nt][2], s[nt][3]));
            }
            mloc_lo = fmaxf(mloc_lo, __shfl_xor_sync(0xffffffffu, mloc_lo, 1));
            mloc_lo = fmaxf(mloc_lo, __shfl_xor_sync(0xffffffffu, mloc_lo, 2));
            mloc_hi = fmaxf(mloc_hi, __shfl_xor_sync(0xffffffffu, mloc_hi, 1));
            mloc_hi = fmaxf(mloc_hi, __shfl_xor_sync(0xffffffffu, mloc_hi, 2));

            const float mn_lo = fmaxf(m_lo, mloc_lo);
            const float mn_hi = fmaxf(m_hi, mloc_hi);
            const float a_lo = __expf(m_lo - mn_lo);
            const float a_hi = __expf(m_hi - mn_hi);
            m_lo = mn_lo; m_hi = mn_hi;

            // exp in place; accumulate row sums
            float ps_lo = 0.f, ps_hi = 0.f;
#pragma unroll
            for (int nt = 0; nt < 8; nt++) {
                s[nt][0] = __expf(s[nt][0] - mn_lo);
                s[nt][1] = __expf(s[nt][1] - mn_lo);
                s[nt][2] = __expf(s[nt][2] - mn_hi);
                s[nt][3] = __expf(s[nt][3] - mn_hi);
                ps_lo += s[nt][0] + s[nt][1];
                ps_hi += s[nt][2] + s[nt][3];
            }
            ps_lo += __shfl_xor_sync(0xffffffffu, ps_lo, 1);
            ps_lo += __shfl_xor_sync(0xffffffffu, ps_lo, 2);
            ps_hi += __shfl_xor_sync(0xffffffffu, ps_hi, 1);
            ps_hi += __shfl_xor_sync(0xffffffffu, ps_hi, 2);
            l_lo = a_lo * l_lo + ps_lo;
            l_hi = a_hi * l_hi + ps_hi;

#pragma unroll
            for (int nt = 0; nt < 8; nt++) {
                o[nt][0] *= a_lo; o[nt][1] *= a_lo;
                o[nt][2] *= a_hi; o[nt][3] *= a_hi;
            }

            // ---- round P (in place) ----
#pragma unroll
            for (int nt = 0; nt < 8; nt++) {
                s[nt][0] = tf2f(s[nt][0]); s[nt][1] = tf2f(s[nt][1]);
                s[nt][2] = tf2f(s[nt][2]); s[nt][3] = tf2f(s[nt][3]);
            }

            // ---- O += P V via shuffle re-fragmentation ----
            const int bse  = lane & ~3;
            const int src0 = bse | (c >> 1);
            const int src1 = src0 + 2;
            const bool odd = (c & 1) != 0;
#pragma unroll
            for (int ks = 0; ks < 8; ks++) {
                const int kc = ks * 8;
                const float v0 = __shfl_sync(0xffffffffu, s[ks][0], src0);
                const float v1 = __shfl_sync(0xffffffffu, s[ks][1], src0);
                const float v2 = __shfl_sync(0xffffffffu, s[ks][2], src0);
                const float v3 = __shfl_sync(0xffffffffu, s[ks][3], src0);
                const float w0 = __shfl_sync(0xffffffffu, s[ks][0], src1);
                const float w1 = __shfl_sync(0xffffffffu, s[ks][1], src1);
                const float w2 = __shfl_sync(0xffffffffu, s[ks][2], src1);
                const float w3 = __shfl_sync(0xffffffffu, s[ks][3], src1);
                uint32_t af[4];
                af[0] = __float_as_uint(odd ? v1 : v0);  // P[r   ][kc+c]
                af[1] = __float_as_uint(odd ? v3 : v2);  // P[r+8 ][kc+c]
                af[2] = __float_as_uint(odd ? w1 : w0);  // P[r   ][kc+c+4]
                af[3] = __float_as_uint(odd ? w3 : w2);  // P[r+8 ][kc+c+4]
#pragma unroll
                for (int nt = 0; nt < 8; nt++) {
                    const uint32_t b0 = __float_as_uint(Vs[kc + c    ][nt * 8 + r]);
                    const uint32_t b1 = __float_as_uint(Vs[kc + c + 4][nt * 8 + r]);
                    mma_tf32(o[nt], af, b0, b1);
                }
            }
        }
    }

    // ---- epilogue: normalize, round (feeds out-proj), store ----
    const float inv_lo = 1.f / l_lo;
    const float inv_hi = 1.f / l_hi;
    float* olo = g_O + (size_t)(b_ * SS + qg_lo) * DD + h * HD;
    float* ohi = g_O + (size_t)(b_ * SS + qg_hi) * DD + h * HD;
#pragma unroll
    for (int nt = 0; nt < 8; nt++) {
        const int dc = nt * 8 + 2 * c;
        *(float2*)&olo[dc] = make_float2(tf2f(o[nt][0] * inv_lo), tf2f(o[nt][1] * inv_lo));
        *(float2*)&ohi[dc] = make_float2(tf2f(o[nt][2] * inv_hi), tf2f(o[nt][3] * inv_hi));
    }
}

// ---------------------------------------------------------------------------
// Launch
// Inputs: 0:X 1:key_padding_mask 2:Wq 3:bq 4:Wk 5:bk 6:Wv 7:bv 8:Wo 9:bo
// ---------------------------------------------------------------------------
extern "C" void kernel_launch(void* const* d_in, const int* in_sizes, int n_in,
                              void* d_out, int out_size)
{
    const float* X   = (const float*)d_in[0];
    const int*   kpm = (const int*)  d_in[1];
    const float* Wq  = (const float*)d_in[2];
    const float* bq  = (const float*)d_in[3];
    const float* Wk  = (const float*)d_in[4];
    const float* bk  = (const float*)d_in[5];
    const float* Wv  = (const float*)d_in[6];
    const float* bv  = (const float*)d_in[7];
    const float* Wo  = (const float*)d_in[8];
    const float* bo  = (const float*)d_in[9];
    float* out = (float*)d_out;

    float *qp, *kp, *vp, *wqr, *wkr, *wvr, *wor;
    cudaGetSymbolAddress((void**)&qp,  g_Q);
    cudaGetSymbolAddress((void**)&kp,  g_K);
    cudaGetSymbolAddress((void**)&vp,  g_V);
    cudaGetSymbolAddress((void**)&wqr, g_Wqr);
    cudaGetSymbolAddress((void**)&wkr, g_Wkr);
    cudaGetSymbolAddress((void**)&wvr, g_Wvr);
    cudaGetSymbolAddress((void**)&wor, g_Wor);

    cudaFuncSetAttribute(gemm_qkv, cudaFuncAttributeMaxDynamicSharedMemorySize, GSM_TOTAL);
    cudaFuncSetAttribute(gemm_out, cudaFuncAttributeMaxDynamicSharedMemorySize, GSM_TOTAL);
    cudaFuncSetAttribute(attn_tf32, cudaFuncAttributeMaxDynamicSharedMemorySize, ASM_TOTAL);

    // Prepass: round all 4 weight matrices (one launch)
    round_w<<<4 * WQUAD / 256, 256>>>(Wq, Wk, Wv, Wo, wqr, wkr, wvr, wor);

    // Fused QKV projections
    dim3 gqkv(3 * DD / 128, MTOK / 128);   // (24, 32)
    gemm_qkv<<<gqkv, 256, GSM_TOTAL>>>(X, wqr, wkr, wvr, bq, bk, bv, qp, kp, vp);

    // Attention
    dim3 gattn(SS / 64, BH);               // (32, 32)
    attn_tf32<<<gattn, 128, ASM_TOTAL>>>(kpm);

    // Output projection
    dim3 gout(DD / 128, MTOK / 128);       // (8, 32)
    gemm_out<<<gout, 256, GSM_TOTAL>>>(wor, bo, out);
}

// round 6
// speedup vs baseline: 6.7017x; 1.0284x over previous
#include <cuda_runtime.h>
#include <math.h>
#include <float.h>
#include <stdint.h>

// Problem dims (fixed by the reference)
#define BB  2
#define SS  2048
#define DD  1024
#define HH  16
#define HD  64
#define BH  (BB*HH)          // 32
#define MTOK (BB*SS)         // 4096

// Scratch (device globals: allocation-free rule)
__device__ float g_Q[BH*SS*HD];   // [bh][s][hd]   (tf32-rounded, pre-scaled)
__device__ float g_K[BH*SS*HD];
__device__ float g_V[BH*SS*HD];
__device__ float g_O[MTOK*DD];    // [b*S+s][d]    (tf32-rounded attn out)
__device__ float g_Wqr[DD*DD], g_Wkr[DD*DD], g_Wvr[DD*DD], g_Wor[DD*DD];

// ---------------------------------------------------------------------------
// Helpers
// ---------------------------------------------------------------------------
__device__ __forceinline__ uint32_t f2tf(float x) {
    uint32_t r;
    asm("cvt.rna.tf32.f32 %0, %1;" : "=r"(r) : "f"(x));
    return r;
}
__device__ __forceinline__ float tf2f(float x) {
    return __uint_as_float(f2tf(x));
}
__device__ __forceinline__ float ex2(float x) {   // 2^x, MUFU.EX2
    float y;
    asm("ex2.approx.f32 %0, %1;" : "=f"(y) : "f"(x));
    return y;
}
__device__ __forceinline__ uint32_t smem_u32(const void* p) {
    uint32_t a;
    asm("{ .reg .u64 t; cvta.to.shared.u64 t, %1; cvt.u32.u64 %0, t; }" : "=r"(a) : "l"(p));
    return a;
}
__device__ __forceinline__ void cpa16(uint32_t dst, const void* src) {
    asm volatile("{ .reg .u64 g; cvta.to.global.u64 g, %1; cp.async.cg.shared.global [%0], [g], 16; }"
                 :: "r"(dst), "l"(src));
}
#define CPA_COMMIT() asm volatile("cp.async.commit_group;" ::: "memory")
#define CPA_WAIT0()  asm volatile("cp.async.wait_group 0;" ::: "memory")
#define CPA_WAIT1()  asm volatile("cp.async.wait_group 1;" ::: "memory")

// D += A * B  (m16n8k8 mma.sync, tf32 inputs, f32 accum)
__device__ __forceinline__ void mma_tf32(float* d, const uint32_t* a, uint32_t b0, uint32_t b1) {
    asm volatile(
        "mma.sync.aligned.m16n8k8.row.col.f32.tf32.tf32.f32 "
        "{%0,%1,%2,%3},{%4,%5,%6,%7},{%8,%9},{%0,%1,%2,%3};"
        : "+f"(d[0]), "+f"(d[1]), "+f"(d[2]), "+f"(d[3])
        : "r"(a[0]), "r"(a[1]), "r"(a[2]), "r"(a[3]), "r"(b0), "r"(b1));
}

// ---------------------------------------------------------------------------
// Prepass: tf32-round the 4 weight matrices in ONE launch.
// ---------------------------------------------------------------------------
#define WQUAD (DD*DD/4)        // 262144 float4 per matrix
__global__ void round_w(const float* __restrict__ wq, const float* __restrict__ wk,
                        const float* __restrict__ wv, const float* __restrict__ wo,
                        float* __restrict__ oq, float* __restrict__ ok,
                        float* __restrict__ ov, float* __restrict__ oo)
{
    const int i   = blockIdx.x * blockDim.x + threadIdx.x;
    const int reg = i >> 18;
    const int loc = i & (WQUAD - 1);
    const float* s = (reg == 0) ? wq : (reg == 1) ? wk : (reg == 2) ? wv : wo;
    float*       d = (reg == 0) ? oq : (reg == 1) ? ok : (reg == 2) ? ov : oo;
    float4 v = ((const float4*)s)[loc];
    v.x = tf2f(v.x); v.y = tf2f(v.y); v.z = tf2f(v.z); v.w = tf2f(v.w);
    ((float4*)d)[loc] = v;
}

// ---------------------------------------------------------------------------
// GEMM core: tf32 mma.sync, 3-stage cp.async pipeline, block 128x128,
// k-chunk 32, 256 thr = 8 warps (4m x 2n), warp tile 32x64.
// CVT_A: tf32-round A fragments in-register. B must be pre-rounded.
// ---------------------------------------------------------------------------
#define GST  18432u                    // one matrix: 128*36*4
#define GSTG 36864u                    // one stage: A + B
#define GSM_TOTAL (3 * 36864)          // 110592

template<int CVT_A, int HEADOUT>
__device__ __forceinline__ void gemm_body(
    const float* __restrict__ A, const float* __restrict__ W,
    const float* __restrict__ bias, float* __restrict__ Cout,
    int m0, int n0, char* smem)
{
    const uint32_t sb = smem_u32(smem);
    const int tid  = threadIdx.x;
    const int warp = tid >> 5;
    const int lane = tid & 31;
    const int r = lane >> 2;
    const int c = lane & 3;
    const int wm = (warp & 3) * 32;
    const int wn = (warp >> 2) * 64;

    float acc[2][8][4];
#pragma unroll
    for (int mt = 0; mt < 2; mt++)
#pragma unroll
        for (int nt = 0; nt < 8; nt++)
#pragma unroll
            for (int i = 0; i < 4; i++) acc[mt][nt][i] = 0.f;

    auto fill = [&](int st, int k0) {
        const uint32_t base = sb + (uint32_t)st * GSTG;
#pragma unroll
        for (int t = 0; t < 4; t++) {
            const int idx = tid + t * 256;
            const int row = idx >> 3;
            const int cf  = (idx & 7) * 4;
            const uint32_t so = (uint32_t)(row * 144 + cf * 4);
            cpa16(base + so,       A + (size_t)(m0 + row) * DD + k0 + cf);
            cpa16(base + GST + so, W + (size_t)(n0 + row) * DD + k0 + cf);
        }
        CPA_COMMIT();
    };

    fill(0, 0);
    fill(1, 32);

    int st = 0, st2 = 2;
    for (int i = 0; i < 32; i++) {
        if (i + 1 < 32) { CPA_WAIT1(); } else { CPA_WAIT0(); }
        __syncthreads();
        if (i + 2 < 32) fill(st2, (i + 2) * 32);

        float (*As)[36] = (float(*)[36])(smem + st * GSTG);
        float (*Bs)[36] = (float(*)[36])(smem + st * GSTG + GST);

#pragma unroll
        for (int ks = 0; ks < 4; ks++) {
            const int kc = ks * 8;
            uint32_t bf[8][2];
#pragma unroll
            for (int nt = 0; nt < 8; nt++) {
                bf[nt][0] = __float_as_uint(Bs[wn + nt * 8 + r][kc + c]);
                bf[nt][1] = __float_as_uint(Bs[wn + nt * 8 + r][kc + c + 4]);
            }
            uint32_t af[2][4];
#pragma unroll
            for (int mt = 0; mt < 2; mt++) {
                const int mr = wm + mt * 16 + r;
                if (CVT_A) {
                    af[mt][0] = f2tf(As[mr    ][kc + c]);
                    af[mt][1] = f2tf(As[mr + 8][kc + c]);
                    af[mt][2] = f2tf(As[mr    ][kc + c + 4]);
                    af[mt][3] = f2tf(As[mr + 8][kc + c + 4]);
                } else {
                    af[mt][0] = __float_as_uint(As[mr    ][kc + c]);
                    af[mt][1] = __float_as_uint(As[mr + 8][kc + c]);
                    af[mt][2] = __float_as_uint(As[mr    ][kc + c + 4]);
                    af[mt][3] = __float_as_uint(As[mr + 8][kc + c + 4]);
                }
            }
#pragma unroll
            for (int mt = 0; mt < 2; mt++)
#pragma unroll
                for (int nt = 0; nt < 8; nt++)
                    mma_tf32(acc[mt][nt], af[mt], bf[nt][0], bf[nt][1]);
        }
        st  = (st  == 2) ? 0 : st  + 1;
        st2 = (st2 == 2) ? 0 : st2 + 1;
    }

#pragma unroll
    for (int mt = 0; mt < 2; mt++) {
        const int m_lo = m0 + wm + mt * 16 + r;
        const int m_hi = m_lo + 8;
#pragma unroll
        for (int nt = 0; nt < 8; nt++) {
            const int ng = n0 + wn + nt * 8 + 2 * c;
            const float b0 = bias[ng], b1 = bias[ng + 1];
            if (HEADOUT) {   // rounded, head-major scatter (HEADOUT==2: also scale Q)
                const float sc = (HEADOUT == 2) ? 0.18033688011112042f : 1.f;  // 0.125*log2(e)
                float2 lo = make_float2(tf2f((acc[mt][nt][0] + b0) * sc), tf2f((acc[mt][nt][1] + b1) * sc));
                float2 hi = make_float2(tf2f((acc[mt][nt][2] + b0) * sc), tf2f((acc[mt][nt][3] + b1) * sc));
                const int h  = ng >> 6;
                const int hd = ng & 63;
                const int blo = m_lo >> 11, slo = m_lo & 2047;
                const int bhi = m_hi >> 11, shi = m_hi & 2047;
                *(float2*)&Cout[(((size_t)(blo * HH + h) * SS) + slo) * HD + hd] = lo;
                *(float2*)&Cout[(((size_t)(bhi * HH + h) * SS) + shi) * HD + hd] = hi;
            } else {         // exact fp32, row-major (final output)
                *(float2*)&Cout[(size_t)m_lo * DD + ng] = make_float2(acc[mt][nt][0] + b0, acc[mt][nt][1] + b1);
                *(float2*)&Cout[(size_t)m_hi * DD + ng] = make_float2(acc[mt][nt][2] + b0, acc[mt][nt][3] + b1);
            }
        }
    }
}

// Fused QKV: grid (24, 32); virtual n picks matrix. Q gets 0.125*log2e scale.
__global__ __launch_bounds__(256, 2)
void gemm_qkv(const float* __restrict__ X,
              const float* __restrict__ wq, const float* __restrict__ wk, const float* __restrict__ wv,
              const float* __restrict__ bq, const float* __restrict__ bk, const float* __restrict__ bv,
              float* __restrict__ Qo, float* __restrict__ Ko, float* __restrict__ Vo)
{
    extern __shared__ char smem[];
    const int n0v   = blockIdx.x * 128;
    const int which = n0v >> 10;
    const int n0    = n0v & 1023;
    if (which == 0) {
        gemm_body<1, 2>(X, wq, bq, Qo, blockIdx.y * 128, n0, smem);   // scaled Q
    } else {
        const float* W    = (which == 1) ? wk : wv;
        const float* bias = (which == 1) ? bk : bv;
        float*       Out  = (which == 1) ? Ko : Vo;
        gemm_body<1, 1>(X, W, bias, Out, blockIdx.y * 128, n0, smem);
    }
}

// Output projection: A = g_O (pre-rounded), exact fp32 out.
__global__ __launch_bounds__(256, 2)
void gemm_out(const float* __restrict__ wo, const float* __restrict__ bo,
              float* __restrict__ Cout)
{
    extern __shared__ char smem[];
    gemm_body<0, 0>((const float*)g_O, wo, bo, Cout, blockIdx.y * 128, blockIdx.x * 128, smem);
}

// ---------------------------------------------------------------------------
// Flash attention, tf32 mma.sync, 64-key tiles, 2-stage cp.async,
// shuffle-based P re-fragmentation, base-2 softmax (Q pre-scaled by log2e/8).
// Block: 64 q rows of one (b,h), 128 threads = 4 warps x 16 q rows.
// Stage: K[64][68] @0 (17408), V[64][72] @17408 (18432), mask[64] @35840 (256)
// ---------------------------------------------------------------------------
#define AKOFF 0u
#define AVOFF 17408u
#define AMOFF 35840u
#define ASTG  36096u
#define ASM_TOTAL (2 * 36096)     // 72192

__global__ __launch_bounds__(128, 3)
void attn_tf32(const int* __restrict__ kpm)
{
    extern __shared__ char smem[];
    const uint32_t sb = smem_u32(smem);

    const int qt = gridDim.x - 1 - blockIdx.x;   // heavy causal blocks first
    const int bh = blockIdx.y;
    const int b_ = bh >> 4;
    const int h  = bh & 15;
    const int tid  = threadIdx.x;
    const int warp = tid >> 5;
    const int lane = tid & 31;
    const int r = lane >> 2;
    const int c = lane & 3;
    const int q0 = qt * 64;
    const int qg_lo = q0 + warp * 16 + r;
    const int qg_hi = qg_lo + 8;

    auto fill = [&](int st, int kt) {
        const int kbase = kt * 64;
        const uint32_t base = sb + (uint32_t)st * ASTG;
#pragma unroll
        for (int i = 0; i < 8; i++) {
            const int idx = tid + i * 128;
            const int kr  = idx >> 4;
            const int cf  = (idx & 15) * 4;
            cpa16(base + AKOFF + (uint32_t)(kr * 272 + cf * 4),
                  g_K + (size_t)(bh * SS + kbase + kr) * HD + cf);
            cpa16(base + AVOFF + (uint32_t)(kr * 288 + cf * 4),
                  g_V + (size_t)(bh * SS + kbase + kr) * HD + cf);
        }
        if (tid < 16)
            cpa16(base + AMOFF + tid * 16, kpm + (size_t)b_ * SS + kbase + tid * 4);
        CPA_COMMIT();
    };

    // Q fragments: g_Q already tf32-rounded AND pre-scaled by 0.125*log2(e)
    uint32_t qf[8][4];
    {
        const float* qlo = g_Q + (size_t)(bh * SS + qg_lo) * HD;
        const float* qhi = g_Q + (size_t)(bh * SS + qg_hi) * HD;
#pragma unroll
        for (int ks = 0; ks < 8; ks++) {
            qf[ks][0] = __float_as_uint(qlo[ks * 8 + c]);
            qf[ks][1] = __float_as_uint(qhi[ks * 8 + c]);
            qf[ks][2] = __float_as_uint(qlo[ks * 8 + c + 4]);
            qf[ks][3] = __float_as_uint(qhi[ks * 8 + c + 4]);
        }
    }

    float o[8][4];
#pragma unroll
    for (int nt = 0; nt < 8; nt++)
#pragma unroll
        for (int i = 0; i < 4; i++) o[nt][i] = 0.f;
    float m_lo = -1e30f, m_hi = -1e30f, l_lo = 0.f, l_hi = 0.f;

    const int kt_max = qt;
    fill(0, 0);

    for (int kt = 0; kt <= kt_max; kt++) {
        CPA_WAIT0();
        __syncthreads();
        if (kt + 1 <= kt_max) fill((kt + 1) & 1, kt + 1);

        const uint32_t base = (uint32_t)(kt & 1) * ASTG;
        float (*Ks)[68] = (float(*)[68])(smem + base + AKOFF);
        float (*Vs)[72] = (float(*)[72])(smem + base + AVOFF);
        const int* mk   = (const int*)  (smem + base + AMOFF);

        const int kbase = kt * 64;
        const bool mymask = (mk[lane] != 0) || (mk[lane + 32] != 0);
        const int  skip = __all_sync(0xffffffffu, (mk[lane] != 0) && (mk[lane + 32] != 0));
        const int  anym = __any_sync(0xffffffffu, mymask);

        if (!skip) {
            // ---- scores: S = Q K^T (log2 domain) ----
            float s[8][4];
#pragma unroll
            for (int nt = 0; nt < 8; nt++)
#pragma unroll
                for (int i = 0; i < 4; i++) s[nt][i] = 0.f;
#pragma unroll
            for (int ks = 0; ks < 8; ks++) {
                const int kc = ks * 8;
#pragma unroll
                for (int nt = 0; nt < 8; nt++) {
                    const uint32_t b0 = __float_as_uint(Ks[nt * 8 + r][kc + c]);
                    const uint32_t b1 = __float_as_uint(Ks[nt * 8 + r][kc + c + 4]);
                    mma_tf32(s[nt], qf[ks], b0, b1);
                }
            }

            // ---- mask (slow path only) + row max ----
            float mloc_lo = -1e30f, mloc_hi = -1e30f;
            if (kt < qt && !anym) {
                // fast path: tile fully visible & unpadded
#pragma unroll
                for (int nt = 0; nt < 8; nt++) {
                    mloc_lo = fmaxf(mloc_lo, fmaxf(s[nt][0], s[nt][1]));
                    mloc_hi = fmaxf(mloc_hi, fmaxf(s[nt][2], s[nt][3]));
                }
            } else {
#pragma unroll
                for (int nt = 0; nt < 8; nt++) {
                    const int kc0 = nt * 8 + 2 * c;
                    const bool bad0 = mk[kc0] != 0;
                    const bool bad1 = mk[kc0 + 1] != 0;
                    const int kg0 = kbase + kc0, kg1 = kg0 + 1;
                    s[nt][0] = (bad0 || kg0 > qg_lo) ? -1e30f : s[nt][0];
                    s[nt][1] = (bad1 || kg1 > qg_lo) ? -1e30f : s[nt][1];
                    s[nt][2] = (bad0 || kg0 > qg_hi) ? -1e30f : s[nt][2];
                    s[nt][3] = (bad1 || kg1 > qg_hi) ? -1e30f : s[nt][3];
                    mloc_lo = fmaxf(mloc_lo, fmaxf(s[nt][0], s[nt][1]));
                    mloc_hi = fmaxf(mloc_hi, fmaxf(s[nt][2], s[nt][3]));
                }
            }
            mloc_lo = fmaxf(mloc_lo, __shfl_xor_sync(0xffffffffu, mloc_lo, 1));
            mloc_lo = fmaxf(mloc_lo, __shfl_xor_sync(0xffffffffu, mloc_lo, 2));
            mloc_hi = fmaxf(mloc_hi, __shfl_xor_sync(0xffffffffu, mloc_hi, 1));
            mloc_hi = fmaxf(mloc_hi, __shfl_xor_sync(0xffffffffu, mloc_hi, 2));

            const float mn_lo = fmaxf(m_lo, mloc_lo);
            const float mn_hi = fmaxf(m_hi, mloc_hi);
            const float a_lo = ex2(m_lo - mn_lo);
            const float a_hi = ex2(m_hi - mn_hi);
            m_lo = mn_lo; m_hi = mn_hi;

            // exp2 in place; accumulate row sums
            float ps_lo = 0.f, ps_hi = 0.f;
#pragma unroll
            for (int nt = 0; nt < 8; nt++) {
                s[nt][0] = ex2(s[nt][0] - mn_lo);
                s[nt][1] = ex2(s[nt][1] - mn_lo);
                s[nt][2] = ex2(s[nt][2] - mn_hi);
                s[nt][3] = ex2(s[nt][3] - mn_hi);
                ps_lo += s[nt][0] + s[nt][1];
                ps_hi += s[nt][2] + s[nt][3];
            }
            ps_lo += __shfl_xor_sync(0xffffffffu, ps_lo, 1);
            ps_lo += __shfl_xor_sync(0xffffffffu, ps_lo, 2);
            ps_hi += __shfl_xor_sync(0xffffffffu, ps_hi, 1);
            ps_hi += __shfl_xor_sync(0xffffffffu, ps_hi, 2);
            l_lo = a_lo * l_lo + ps_lo;
            l_hi = a_hi * l_hi + ps_hi;

#pragma unroll
            for (int nt = 0; nt < 8; nt++) {
                o[nt][0] *= a_lo; o[nt][1] *= a_lo;
                o[nt][2] *= a_hi; o[nt][3] *= a_hi;
            }

            // ---- round P (in place) ----
#pragma unroll
            for (int nt = 0; nt < 8; nt++) {
                s[nt][0] = tf2f(s[nt][0]); s[nt][1] = tf2f(s[nt][1]);
                s[nt][2] = tf2f(s[nt][2]); s[nt][3] = tf2f(s[nt][3]);
            }

            // ---- O += P V via shuffle re-fragmentation ----
            const int bse  = lane & ~3;
            const int src0 = bse | (c >> 1);
            const int src1 = src0 + 2;
            const bool odd = (c & 1) != 0;
#pragma unroll
            for (int ks = 0; ks < 8; ks++) {
                const int kc = ks * 8;
                const float v0 = __shfl_sync(0xffffffffu, s[ks][0], src0);
                const float v1 = __shfl_sync(0xffffffffu, s[ks][1], src0);
                const float v2 = __shfl_sync(0xffffffffu, s[ks][2], src0);
                const float v3 = __shfl_sync(0xffffffffu, s[ks][3], src0);
                const float w0 = __shfl_sync(0xffffffffu, s[ks][0], src1);
                const float w1 = __shfl_sync(0xffffffffu, s[ks][1], src1);
                const float w2 = __shfl_sync(0xffffffffu, s[ks][2], src1);
                const float w3 = __shfl_sync(0xffffffffu, s[ks][3], src1);
                uint32_t af[4];
                af[0] = __float_as_uint(odd ? v1 : v0);
                af[1] = __float_as_uint(odd ? v3 : v2);
                af[2] = __float_as_uint(odd ? w1 : w0);
                af[3] = __float_as_uint(odd ? w3 : w2);
#pragma unroll
                for (int nt = 0; nt < 8; nt++) {
                    const uint32_t b0 = __float_as_uint(Vs[kc + c    ][nt * 8 + r]);
                    const uint32_t b1 = __float_as_uint(Vs[kc + c + 4][nt * 8 + r]);
                    mma_tf32(o[nt], af, b0, b1);
                }
            }
        }
    }

    // ---- epilogue: normalize, round (feeds out-proj), store ----
    const float inv_lo = 1.f / l_lo;
    const float inv_hi = 1.f / l_hi;
    float* olo = g_O + (size_t)(b_ * SS + qg_lo) * DD + h * HD;
    float* ohi = g_O + (size_t)(b_ * SS + qg_hi) * DD + h * HD;
#pragma unroll
    for (int nt = 0; nt < 8; nt++) {
        const int dc = nt * 8 + 2 * c;
        *(float2*)&olo[dc] = make_float2(tf2f(o[nt][0] * inv_lo), tf2f(o[nt][1] * inv_lo));
        *(float2*)&ohi[dc] = make_float2(tf2f(o[nt][2] * inv_hi), tf2f(o[nt][3] * inv_hi));
    }
}

// ---------------------------------------------------------------------------
// Launch
// Inputs: 0:X 1:key_padding_mask 2:Wq 3:bq 4:Wk 5:bk 6:Wv 7:bv 8:Wo 9:bo
// ---------------------------------------------------------------------------
extern "C" void kernel_launch(void* const* d_in, const int* in_sizes, int n_in,
                              void* d_out, int out_size)
{
    const float* X   = (const float*)d_in[0];
    const int*   kpm = (const int*)  d_in[1];
    const float* Wq  = (const float*)d_in[2];
    const float* bq  = (const float*)d_in[3];
    const float* Wk  = (const float*)d_in[4];
    const float* bk  = (const float*)d_in[5];
    const float* Wv  = (const float*)d_in[6];
    const float* bv  = (const float*)d_in[7];
    const float* Wo  = (const float*)d_in[8];
    const float* bo  = (const float*)d_in[9];
    float* out = (float*)d_out;

    float *qp, *kp, *vp, *wqr, *wkr, *wvr, *wor;
    cudaGetSymbolAddress((void**)&qp,  g_Q);
    cudaGetSymbolAddress((void**)&kp,  g_K);
    cudaGetSymbolAddress((void**)&vp,  g_V);
    cudaGetSymbolAddress((void**)&wqr, g_Wqr);
    cudaGetSymbolAddress((void**)&wkr, g_Wkr);
    cudaGetSymbolAddress((void**)&wvr, g_Wvr);
    cudaGetSymbolAddress((void**)&wor, g_Wor);

    cudaFuncSetAttribute(gemm_qkv, cudaFuncAttributeMaxDynamicSharedMemorySize, GSM_TOTAL);
    cudaFuncSetAttribute(gemm_out, cudaFuncAttributeMaxDynamicSharedMemorySize, GSM_TOTAL);
    cudaFuncSetAttribute(attn_tf32, cudaFuncAttributeMaxDynamicSharedMemorySize, ASM_TOTAL);

    // Prepass: round all 4 weight matrices (one launch)
    round_w<<<4 * WQUAD / 256, 256>>>(Wq, Wk, Wv, Wo, wqr, wkr, wvr, wor);

    // Fused QKV projections
    dim3 gqkv(3 * DD / 128, MTOK / 128);   // (24, 32)
    gemm_qkv<<<gqkv, 256, GSM_TOTAL>>>(X, wqr, wkr, wvr, bq, bk, bv, qp, kp, vp);

    // Attention
    dim3 gattn(SS / 64, BH);               // (32, 32)
    attn_tf32<<<gattn, 128, ASM_TOTAL>>>(kpm);

    // Output projection
    dim3 gout(DD / 128, MTOK / 128);       // (8, 32)
    gemm_out<<<gout, 256, GSM_TOTAL>>>(wor, bo, out);
}

// round 8
// speedup vs baseline: 13.2225x; 1.9730x over previous
#include <cuda_runtime.h>
#include <cuda_fp16.h>
#include <math.h>
#include <float.h>
#include <stdint.h>

// Problem dims (fixed by the reference)
#define BB  2
#define SS  2048
#define DD  1024
#define HH  16
#define HD  64
#define BH  (BB*HH)          // 32
#define MTOK (BB*SS)         // 4096

// Scratch (device globals: allocation-free rule)
__device__ __half g_Qh[BH*SS*HD];   // [bh][s][hd] (half, pre-scaled by 0.125*log2e)
__device__ __half g_Kh[BH*SS*HD];
__device__ __half g_Vh[BH*SS*HD];
__device__ __half g_Oh[MTOK*DD];    // [tok][d] attn out (half)
__device__ __half g_Xh[MTOK*DD];    // X rounded to half
__device__ __half g_Wqh[DD*DD], g_Wkh[DD*DD], g_Wvh[DD*DD], g_Woh[DD*DD];

// ---------------------------------------------------------------------------
// Helpers
// ---------------------------------------------------------------------------
__device__ __forceinline__ float ex2(float x) {
    float y; asm("ex2.approx.f32 %0, %1;" : "=f"(y) : "f"(x)); return y;
}
__device__ __forceinline__ uint32_t smem_u32(const void* p) {
    uint32_t a;
    asm("{ .reg .u64 t; cvta.to.shared.u64 t, %1; cvt.u32.u64 %0, t; }" : "=r"(a) : "l"(p));
    return a;
}
__device__ __forceinline__ void cpa16(uint32_t dst, const void* src) {
    asm volatile("{ .reg .u64 g; cvta.to.global.u64 g, %1; cp.async.cg.shared.global [%0], [g], 16; }"
                 :: "r"(dst), "l"(src));
}
#define CPA_COMMIT() asm volatile("cp.async.commit_group;" ::: "memory")
#define CPA_WAIT0()  asm volatile("cp.async.wait_group 0;" ::: "memory")
#define CPA_WAIT1()  asm volatile("cp.async.wait_group 1;" ::: "memory")

// swizzled byte address: 128B rows, 16B chunks, chunk ^= row&7
__device__ __forceinline__ uint32_t swz(uint32_t base, int row, int chunk) {
    return base + (uint32_t)(row * 128) + (uint32_t)(((chunk ^ (row & 7)) << 4));
}

__device__ __forceinline__ void ldm_x4(uint32_t& r0, uint32_t& r1, uint32_t& r2, uint32_t& r3, uint32_t a) {
    asm volatile("ldmatrix.sync.aligned.m8n8.x4.shared.b16 {%0,%1,%2,%3}, [%4];"
                 : "=r"(r0), "=r"(r1), "=r"(r2), "=r"(r3) : "r"(a));
}
__device__ __forceinline__ void ldm_x4t(uint32_t& r0, uint32_t& r1, uint32_t& r2, uint32_t& r3, uint32_t a) {
    asm volatile("ldmatrix.sync.aligned.m8n8.x4.trans.shared.b16 {%0,%1,%2,%3}, [%4];"
                 : "=r"(r0), "=r"(r1), "=r"(r2), "=r"(r3) : "r"(a));
}

// D += A * B  (m16n8k16 fp16 inputs, f32 accum)
__device__ __forceinline__ void mma_f16(float* d, const uint32_t* a, uint32_t b0, uint32_t b1) {
    asm volatile(
        "mma.sync.aligned.m16n8k16.row.col.f32.f16.f16.f32 "
        "{%0,%1,%2,%3},{%4,%5,%6,%7},{%8,%9},{%0,%1,%2,%3};"
        : "+f"(d[0]), "+f"(d[1]), "+f"(d[2]), "+f"(d[3])
        : "r"(a[0]), "r"(a[1]), "r"(a[2]), "r"(a[3]), "r"(b0), "r"(b1));
}

__device__ __forceinline__ uint32_t pack_h2(float lo, float hi) {
    __half2 h = __floats2half2_rn(lo, hi);
    return *(uint32_t*)&h;
}

// ---------------------------------------------------------------------------
// Prepass: convert X + 4 weight matrices to half (one launch).
// ---------------------------------------------------------------------------
#define XQUAD (MTOK*DD/4)      // 1048576
#define WQUAD (DD*DD/4)        // 262144
__global__ void prep_h(const float* __restrict__ X,
                       const float* __restrict__ wq, const float* __restrict__ wk,
                       const float* __restrict__ wv, const float* __restrict__ wo)
{
    const int i = blockIdx.x * blockDim.x + threadIdx.x;   // 0 .. XQUAD+4*WQUAD-1
    const float* s; __half* d; int loc;
    if (i < XQUAD) { s = X; d = g_Xh; loc = i; }
    else {
        const int j = i - XQUAD;
        const int reg = j >> 18;
        loc = j & (WQUAD - 1);
        s = (reg == 0) ? wq : (reg == 1) ? wk : (reg == 2) ? wv : wo;
        d = (reg == 0) ? g_Wqh : (reg == 1) ? g_Wkh : (reg == 2) ? g_Wvh : g_Woh;
    }
    float4 v = ((const float4*)s)[loc];
    uint2 u;
    u.x = pack_h2(v.x, v.y);
    u.y = pack_h2(v.z, v.w);
    ((uint2*)d)[loc] = u;
}

// ---------------------------------------------------------------------------
// fp16 NT GEMM: C[m][n] = sum_k A[m][k]*W[n][k] + bias[n] (fp32 accum)
// Block 128x128, k-chunk 64 halves (128B swizzled rows), 3-stage cp.async.
// 256 thr = 8 warps (4m x 2n), warp tile 32x64. ldmatrix operand loads.
// HEADOUT 0: fp32 row-major.  1: half head-major.  2: half head-major *qscale.
// ---------------------------------------------------------------------------
#define GST  16384u                    // one matrix per stage: 128*128B
#define GSTG 32768u
#define GSM_TOTAL (3 * 32768)          // 98304

template<int HEADOUT>
__device__ __forceinline__ void gemm_body(
    const __half* __restrict__ A, const __half* __restrict__ W,
    const float* __restrict__ bias, void* __restrict__ Cout,
    int m0, int n0, char* smem)
{
    const uint32_t sb = smem_u32(smem);
    const int tid  = threadIdx.x;
    const int warp = tid >> 5;
    const int lane = tid & 31;
    const int r = lane >> 2;
    const int c = lane & 3;
    const int wm = (warp & 3) * 32;
    const int wn = (warp >> 2) * 64;
    const int lrow = (lane & 7) + (lane & 8);   // ldmatrix row-within-16 for this lane
    const int lsel = lane >> 4;                 // ldmatrix chunk-half select

    float acc[2][8][4];
#pragma unroll
    for (int mt = 0; mt < 2; mt++)
#pragma unroll
        for (int nt = 0; nt < 8; nt++)
#pragma unroll
            for (int i = 0; i < 4; i++) acc[mt][nt][i] = 0.f;

    auto fill = [&](int st, int k0) {
        const uint32_t base = sb + (uint32_t)st * GSTG;
#pragma unroll
        for (int t = 0; t < 4; t++) {
            const int idx = tid + t * 256;     // 0..1023
            const int row = idx >> 3;          // 0..127
            const int ch  = idx & 7;           // 16B chunk = 8 halves
            cpa16(swz(base, row, ch),       A + (size_t)(m0 + row) * DD + k0 + ch * 8);
            cpa16(swz(base + GST, row, ch), W + (size_t)(n0 + row) * DD + k0 + ch * 8);
        }
        CPA_COMMIT();
    };

    fill(0, 0);
    fill(1, 64);

    int st = 0, st2 = 2;
    for (int i = 0; i < 16; i++) {
        if (i + 1 < 16) { CPA_WAIT1(); } else { CPA_WAIT0(); }
        __syncthreads();
        if (i + 2 < 16) fill(st2, (i + 2) * 64);

        const uint32_t Ab = sb + (uint32_t)st * GSTG;
        const uint32_t Bb = Ab + GST;

#pragma unroll
        for (int ks = 0; ks < 4; ks++) {       // 4 x k16
            const int ch = ks * 2 + lsel;
            uint32_t af[2][4];
#pragma unroll
            for (int mt = 0; mt < 2; mt++)
                ldm_x4(af[mt][0], af[mt][1], af[mt][2], af[mt][3],
                       swz(Ab, wm + mt * 16 + lrow, ch));
            uint32_t bf[8][2];
#pragma unroll
            for (int np = 0; np < 4; np++) {
                uint32_t r0, r1, r2, r3;
                ldm_x4(r0, r1, r2, r3, swz(Bb, wn + np * 16 + lrow, ch));
                bf[2*np][0] = r0; bf[2*np][1] = r2;
                bf[2*np+1][0] = r1; bf[2*np+1][1] = r3;
            }
#pragma unroll
            for (int mt = 0; mt < 2; mt++)
#pragma unroll
                for (int nt = 0; nt < 8; nt++)
                    mma_f16(acc[mt][nt], af[mt], bf[nt][0], bf[nt][1]);
        }
        st  = (st  == 2) ? 0 : st  + 1;
        st2 = (st2 == 2) ? 0 : st2 + 1;
    }

#pragma unroll
    for (int mt = 0; mt < 2; mt++) {
        const int m_lo = m0 + wm + mt * 16 + r;
        const int m_hi = m_lo + 8;
#pragma unroll
        for (int nt = 0; nt < 8; nt++) {
            const int ng = n0 + wn + nt * 8 + 2 * c;
            const float b0 = bias[ng], b1 = bias[ng + 1];
            if (HEADOUT) {
                const float sc = (HEADOUT == 2) ? 0.18033688011112042f : 1.f;  // 0.125*log2(e)
                const uint32_t lo = pack_h2((acc[mt][nt][0] + b0) * sc, (acc[mt][nt][1] + b1) * sc);
                const uint32_t hi = pack_h2((acc[mt][nt][2] + b0) * sc, (acc[mt][nt][3] + b1) * sc);
                const int h  = ng >> 6;
                const int hd = ng & 63;
                const int blo = m_lo >> 11, slo = m_lo & 2047;
                const int bhi = m_hi >> 11, shi = m_hi & 2047;
                __half* Ch = (__half*)Cout;
                *(uint32_t*)&Ch[(((size_t)(blo * HH + h) * SS) + slo) * HD + hd] = lo;
                *(uint32_t*)&Ch[(((size_t)(bhi * HH + h) * SS) + shi) * HD + hd] = hi;
            } else {
                float* Cf = (float*)Cout;
                *(float2*)&Cf[(size_t)m_lo * DD + ng] = make_float2(acc[mt][nt][0] + b0, acc[mt][nt][1] + b1);
                *(float2*)&Cf[(size_t)m_hi * DD + ng] = make_float2(acc[mt][nt][2] + b0, acc[mt][nt][3] + b1);
            }
        }
    }
}

// Fused QKV: grid (24, 32); virtual n picks matrix. Q scaled.
__global__ __launch_bounds__(256, 2)
void gemm_qkv(const float* __restrict__ bq, const float* __restrict__ bk,
              const float* __restrict__ bv)
{
    extern __shared__ char smem[];
    const int n0v   = blockIdx.x * 128;
    const int which = n0v >> 10;
    const int n0    = n0v & 1023;
    if (which == 0)
        gemm_body<2>(g_Xh, g_Wqh, bq, g_Qh, blockIdx.y * 128, n0, smem);
    else if (which == 1)
        gemm_body<1>(g_Xh, g_Wkh, bk, g_Kh, blockIdx.y * 128, n0, smem);
    else
        gemm_body<1>(g_Xh, g_Wvh, bv, g_Vh, blockIdx.y * 128, n0, smem);
}

// Output projection: A = g_Oh, exact fp32 out.
__global__ __launch_bounds__(256, 2)
void gemm_out(const float* __restrict__ bo, float* __restrict__ Cout)
{
    extern __shared__ char smem[];
    gemm_body<0>(g_Oh, g_Woh, bo, Cout, blockIdx.y * 128, blockIdx.x * 128, smem);
}

// ---------------------------------------------------------------------------
// Flash attention, fp16 mma + ldmatrix, 64-key tiles, 2-stage cp.async,
// base-2 softmax. Block: 64 q rows of one (b,h), 128 thr = 4 warps x 16 rows.
// Stage: K 64x128B @0 (8192), V @8192 (8192), mask 64 ints @16384 (256) -> 16640
// Ps (P as half, 64x128B swizzled) @ 2*16640 = 33280.
// ---------------------------------------------------------------------------
#define AKOFF 0u
#define AVOFF 8192u
#define AMOFF 16384u
#define ASTG  16640u
#define APOFF 33280u
#define ASM_TOTAL (33280 + 8192)    // 41472

__global__ __launch_bounds__(128, 3)
void attn_h(const int* __restrict__ kpm)
{
    extern __shared__ char smem[];
    const uint32_t sb = smem_u32(smem);

    const int qt = gridDim.x - 1 - blockIdx.x;   // heavy causal blocks first
    const int bh = blockIdx.y;
    const int b_ = bh >> 4;
    const int h  = bh & 15;
    const int tid  = threadIdx.x;
    const int warp = tid >> 5;
    const int lane = tid & 31;
    const int r = lane >> 2;
    const int c = lane & 3;
    const int lrow = (lane & 7) + (lane & 8);
    const int lsel = lane >> 4;
    const int q0 = qt * 64;
    const int qr = warp * 16;
    const int qg_lo = q0 + qr + r;
    const int qg_hi = qg_lo + 8;

    auto fill = [&](int st, int kt) {
        const int kbase = kt * 64;
        const uint32_t base = sb + (uint32_t)st * ASTG;
#pragma unroll
        for (int i = 0; i < 4; i++) {
            const int idx = tid + i * 128;   // 0..511
            const int kr  = idx >> 3;        // 0..63
            const int ch  = idx & 7;
            cpa16(swz(base + AKOFF, kr, ch), g_Kh + (size_t)(bh * SS + kbase + kr) * HD + ch * 8);
            cpa16(swz(base + AVOFF, kr, ch), g_Vh + (size_t)(bh * SS + kbase + kr) * HD + ch * 8);
        }
        if (tid < 16)
            cpa16(base + AMOFF + tid * 16, kpm + (size_t)b_ * SS + kbase + tid * 4);
        CPA_COMMIT();
    };

    // Q fragments (half, pre-scaled): qf[ks][0..3] for k16 steps
    uint32_t qf[4][4];
    {
        const __half* qlo = g_Qh + (size_t)(bh * SS + qg_lo) * HD;
        const __half* qhi = g_Qh + (size_t)(bh * SS + qg_hi) * HD;
#pragma unroll
        for (int ks = 0; ks < 4; ks++) {
            qf[ks][0] = *(const uint32_t*)&qlo[ks * 16 + 2 * c];
            qf[ks][1] = *(const uint32_t*)&qhi[ks * 16 + 2 * c];
            qf[ks][2] = *(const uint32_t*)&qlo[ks * 16 + 2 * c + 8];
            qf[ks][3] = *(const uint32_t*)&qhi[ks * 16 + 2 * c + 8];
        }
    }

    float o[8][4];
#pragma unroll
    for (int nt = 0; nt < 8; nt++)
#pragma unroll
        for (int i = 0; i < 4; i++) o[nt][i] = 0.f;
    float m_lo = -1e30f, m_hi = -1e30f, l_lo = 0.f, l_hi = 0.f;

    const int kt_max = qt;
    fill(0, 0);

    for (int kt = 0; kt <= kt_max; kt++) {
        CPA_WAIT0();
        __syncthreads();
        if (kt + 1 <= kt_max) fill((kt + 1) & 1, kt + 1);

        const uint32_t base = sb + (uint32_t)(kt & 1) * ASTG;
        const uint32_t Kb = base + AKOFF;
        const uint32_t Vb = base + AVOFF;
        const int* mk = (const int*)(smem + (kt & 1) * ASTG + AMOFF);
        const uint32_t Pb = sb + APOFF;

        const int kbase = kt * 64;
        const bool mymask = (mk[lane] != 0) || (mk[lane + 32] != 0);
        const int  skip = __all_sync(0xffffffffu, (mk[lane] != 0) && (mk[lane + 32] != 0));
        const int  anym = __any_sync(0xffffffffu, mymask);

        if (!skip) {
            // ---- scores: S = Q K^T (log2 domain) ----
            float s[8][4];
#pragma unroll
            for (int nt = 0; nt < 8; nt++)
#pragma unroll
                for (int i = 0; i < 4; i++) s[nt][i] = 0.f;
#pragma unroll
            for (int ks = 0; ks < 4; ks++) {
                const int ch = ks * 2 + lsel;
                uint32_t bf[8][2];
#pragma unroll
                for (int np = 0; np < 4; np++) {
                    uint32_t r0, r1, r2, r3;
                    ldm_x4(r0, r1, r2, r3, swz(Kb, np * 16 + lrow, ch));
                    bf[2*np][0] = r0; bf[2*np][1] = r2;
                    bf[2*np+1][0] = r1; bf[2*np+1][1] = r3;
                }
#pragma unroll
                for (int nt = 0; nt < 8; nt++)
                    mma_f16(s[nt], qf[ks], bf[nt][0], bf[nt][1]);
            }

            // ---- mask + row max ----
            float mloc_lo = -1e30f, mloc_hi = -1e30f;
            if (kt < qt && !anym) {
#pragma unroll
                for (int nt = 0; nt < 8; nt++) {
                    mloc_lo = fmaxf(mloc_lo, fmaxf(s[nt][0], s[nt][1]));
                    mloc_hi = fmaxf(mloc_hi, fmaxf(s[nt][2], s[nt][3]));
                }
            } else {
#pragma unroll
                for (int nt = 0; nt < 8; nt++) {
                    const int kc0 = nt * 8 + 2 * c;
                    const bool bad0 = mk[kc0] != 0;
                    const bool bad1 = mk[kc0 + 1] != 0;
                    const int kg0 = kbase + kc0, kg1 = kg0 + 1;
                    s[nt][0] = (bad0 || kg0 > qg_lo) ? -1e30f : s[nt][0];
                    s[nt][1] = (bad1 || kg1 > qg_lo) ? -1e30f : s[nt][1];
                    s[nt][2] = (bad0 || kg0 > qg_hi) ? -1e30f : s[nt][2];
                    s[nt][3] = (bad1 || kg1 > qg_hi) ? -1e30f : s[nt][3];
                    mloc_lo = fmaxf(mloc_lo, fmaxf(s[nt][0], s[nt][1]));
                    mloc_hi = fmaxf(mloc_hi, fmaxf(s[nt][2], s[nt][3]));
                }
            }
            mloc_lo = fmaxf(mloc_lo, __shfl_xor_sync(0xffffffffu, mloc_lo, 1));
            mloc_lo = fmaxf(mloc_lo, __shfl_xor_sync(0xffffffffu, mloc_lo, 2));
            mloc_hi = fmaxf(mloc_hi, __shfl_xor_sync(0xffffffffu, mloc_hi, 1));
            mloc_hi = fmaxf(mloc_hi, __shfl_xor_sync(0xffffffffu, mloc_hi, 2));

            const float mn_lo = fmaxf(m_lo, mloc_lo);
            const float mn_hi = fmaxf(m_hi, mloc_hi);
            const float a_lo = ex2(m_lo - mn_lo);
            const float a_hi = ex2(m_hi - mn_hi);
            m_lo = mn_lo; m_hi = mn_hi;

            // exp2 + row sums + P -> half in smem (swizzled, ldmatrix layout)
            float ps_lo = 0.f, ps_hi = 0.f;
#pragma unroll
            for (int nt = 0; nt < 8; nt++) {
                s[nt][0] = ex2(s[nt][0] - mn_lo);
                s[nt][1] = ex2(s[nt][1] - mn_lo);
                s[nt][2] = ex2(s[nt][2] - mn_hi);
                s[nt][3] = ex2(s[nt][3] - mn_hi);
                ps_lo += s[nt][0] + s[nt][1];
                ps_hi += s[nt][2] + s[nt][3];
                const int row0 = qr + r, row1 = qr + r + 8;
                *(uint32_t*)(smem + (swz(Pb, row0, nt) - sb) + 4 * c) = pack_h2(s[nt][0], s[nt][1]);
                *(uint32_t*)(smem + (swz(Pb, row1, nt) - sb) + 4 * c) = pack_h2(s[nt][2], s[nt][3]);
            }
            ps_lo += __shfl_xor_sync(0xffffffffu, ps_lo, 1);
            ps_lo += __shfl_xor_sync(0xffffffffu, ps_lo, 2);
            ps_hi += __shfl_xor_sync(0xffffffffu, ps_hi, 1);
            ps_hi += __shfl_xor_sync(0xffffffffu, ps_hi, 2);
            l_lo = a_lo * l_lo + ps_lo;
            l_hi = a_hi * l_hi + ps_hi;

#pragma unroll
            for (int nt = 0; nt < 8; nt++) {
                o[nt][0] *= a_lo; o[nt][1] *= a_lo;
                o[nt][2] *= a_hi; o[nt][3] *= a_hi;
            }
            __syncwarp();

            // ---- O += P V ----
#pragma unroll
            for (int ks = 0; ks < 4; ks++) {
                uint32_t af[4];
                ldm_x4(af[0], af[1], af[2], af[3],
                       swz(Pb, qr + lrow, ks * 2 + lsel));
                uint32_t bf[8][2];
#pragma unroll
                for (int np = 0; np < 4; np++) {
                    uint32_t r0, r1, r2, r3;
                    // V rows = keys (k axis), chunks = d (n axis); trans load
                    ldm_x4t(r0, r1, r2, r3,
                            swz(Vb, ks * 16 + lrow, 2 * np + lsel));
                    bf[2*np][0] = r0; bf[2*np][1] = r1;
                    bf[2*np+1][0] = r2; bf[2*np+1][1] = r3;
                }
#pragma unroll
                for (int nt = 0; nt < 8; nt++)
                    mma_f16(o[nt], af, bf[nt][0], bf[nt][1]);
            }
            __syncwarp();
        }
    }

    // ---- epilogue: normalize, convert to half, store head-major into g_Oh ----
    const float inv_lo = 1.f / l_lo;
    const float inv_hi = 1.f / l_hi;
    __half* olo = g_Oh + (size_t)(b_ * SS + qg_lo) * DD + h * HD;
    __half* ohi = g_Oh + (size_t)(b_ * SS + qg_hi) * DD + h * HD;
#pragma unroll
    for (int nt = 0; nt < 8; nt++) {
        const int dc = nt * 8 + 2 * c;
        *(uint32_t*)&olo[dc] = pack_h2(o[nt][0] * inv_lo, o[nt][1] * inv_lo);
        *(uint32_t*)&ohi[dc] = pack_h2(o[nt][2] * inv_hi, o[nt][3] * inv_hi);
    }
}

// ---------------------------------------------------------------------------
// Launch
// Inputs: 0:X 1:key_padding_mask 2:Wq 3:bq 4:Wk 5:bk 6:Wv 7:bv 8:Wo 9:bo
// ---------------------------------------------------------------------------
extern "C" void kernel_launch(void* const* d_in, const int* in_sizes, int n_in,
                              void* d_out, int out_size)
{
    const float* X   = (const float*)d_in[0];
    const int*   kpm = (const int*)  d_in[1];
    const float* Wq  = (const float*)d_in[2];
    const float* bq  = (const float*)d_in[3];
    const float* Wk  = (const float*)d_in[4];
    const float* bk  = (const float*)d_in[5];
    const float* Wv  = (const float*)d_in[6];
    const float* bv  = (const float*)d_in[7];
    const float* Wo  = (const float*)d_in[8];
    const float* bo  = (const float*)d_in[9];
    float* out = (float*)d_out;

    cudaFuncSetAttribute(gemm_qkv, cudaFuncAttributeMaxDynamicSharedMemorySize, GSM_TOTAL);
    cudaFuncSetAttribute(gemm_out, cudaFuncAttributeMaxDynamicSharedMemorySize, GSM_TOTAL);
    cudaFuncSetAttribute(attn_h,   cudaFuncAttributeMaxDynamicSharedMemorySize, ASM_TOTAL);

    // Prepass: X + 4 weights -> half
    prep_h<<<(XQUAD + 4 * WQUAD) / 256, 256>>>(X, Wq, Wk, Wv, Wo);

    // Fused QKV projections
    dim3 gqkv(3 * DD / 128, MTOK / 128);   // (24, 32)
    gemm_qkv<<<gqkv, 256, GSM_TOTAL>>>(bq, bk, bv);

    // Attention
    dim3 gattn(SS / 64, BH);               // (32, 32)
    attn_h<<<gattn, 128, ASM_TOTAL>>>(kpm);

    // Output projection
    dim3 gout(DD / 128, MTOK / 128);       // (8, 32)
    gemm_out<<<gout, 256, GSM_TOTAL>>>(bo, out);
}